// round 15
// baseline (speedup 1.0000x reference)
#include <cuda_runtime.h>
#include <cuda_bf16.h>
#include <math.h>
#include <stdint.h>

#define HWX 16384
#define Wd  128
#define Hd  128
#define Bb  2

// ---------------- device scratch (no runtime alloc allowed) ----------------
__device__ float g_sw  [4*Bb*8*HWX];
__device__ __nv_bfloat16 g_Zhi[Bb*1152*HWX];
__device__ __nv_bfloat16 g_Zlo[Bb*1152*HWX];
__device__ float g_part[Bb*21*8*16384];
__device__ float g_Gq  [Bb*4*256*256];
__device__ float g_M   [Bb*128*1024];
__device__ float g_Gc  [Bb*128*128];
__device__ float g_kn  [Bb*4*512];
__device__ float g_qn  [Bb*4*64];
__device__ float g_score[8*64*512];
__device__ float g_ucat[Bb*256*1024];
__device__ float g_wcat[Bb*256*1024];
__device__ __nv_bfloat16 g_whi[Bb*256*1024];
__device__ __nv_bfloat16 g_wlo[Bb*256*1024];
__device__ float g_y   [Bb*256*HWX];
__device__ float g_bn  [512];

__constant__ int c_tr0[21] = {0,0,128, 256,256,384, 512,512,640, 768,768,896,
                              1024,1024,1024,1024,1024,1024,1024,1024, 1024};
__constant__ int c_tc0[21] = {0,128,128, 256,384,384, 512,640,640, 768,896,896,
                              0,128,256,384,512,640,768,896, 1024};

__device__ __forceinline__ float warpsum(float v) {
    #pragma unroll
    for (int o = 16; o > 0; o >>= 1) v += __shfl_xor_sync(0xffffffffu, v, o);
    return v;
}

// ====================== warp-MMA helpers (family-safe PTX) ==================
__device__ __forceinline__ uint32_t smem_u32(const void* p) {
    uint32_t a;
    asm("{ .reg .u64 t; cvta.to.shared.u64 t, %1; cvt.u32.u64 %0, t; }" : "=r"(a) : "l"(p));
    return a;
}
__device__ __forceinline__ void cp16(uint32_t dst, const void* src) {
    asm volatile("cp.async.cg.shared.global [%0], [%1], 16;" :: "r"(dst), "l"(src));
}
__device__ __forceinline__ void cp_commit() {
    asm volatile("cp.async.commit_group;");
}
__device__ __forceinline__ void ldmat4(uint32_t* r, uint32_t addr) {
    asm volatile("ldmatrix.sync.aligned.m8n8.x4.shared.b16 {%0,%1,%2,%3}, [%4];"
        : "=r"(r[0]),"=r"(r[1]),"=r"(r[2]),"=r"(r[3]) : "r"(addr));
}
__device__ __forceinline__ void ldmat4_trans(uint32_t* r, uint32_t addr) {
    asm volatile("ldmatrix.sync.aligned.m8n8.x4.trans.shared.b16 {%0,%1,%2,%3}, [%4];"
        : "=r"(r[0]),"=r"(r[1]),"=r"(r[2]),"=r"(r[3]) : "r"(addr));
}
__device__ __forceinline__ void mma16816(float* d, const uint32_t* a, const uint32_t* b) {
    asm volatile("mma.sync.aligned.m16n8k16.row.col.f32.bf16.bf16.f32 "
        "{%0,%1,%2,%3}, {%4,%5,%6,%7}, {%8,%9}, {%0,%1,%2,%3};"
        : "+f"(d[0]),"+f"(d[1]),"+f"(d[2]),"+f"(d[3])
        : "r"(a[0]),"r"(a[1]),"r"(a[2]),"r"(a[3]), "r"(b[0]),"r"(b[1]));
}

// K-chunk 16: 128 rows x (32B data + 16B pad) -- pitch MUST be 16B-aligned
#define SP16     48
#define TILE16   (128*SP16)          // 6144
#define STAGE16  (4*TILE16)          // 24576 (Ahi,Alo,Bhi,Blo)
#define G_DSMEM  (2*STAGE16)         // 49152 -> 2 CTAs/SM

// ---------------- bf16-split warp-MMA core (NT, 4 warps x 64x64) ------------
__device__ __forceinline__ void mma_core(
    const __nv_bfloat16* __restrict__ Ahi, const __nv_bfloat16* __restrict__ Alo,
    const __nv_bfloat16* __restrict__ Bhi, const __nv_bfloat16* __restrict__ Blo,
    long long pa, long long pb, int nchunks,
    float* __restrict__ out, long long ldo, int diag)
{
    extern __shared__ char dyn[];
    uint32_t sbase = smem_u32(dyn);
    int tid = threadIdx.x, lane = tid & 31, wid = tid >> 5;
    int m0 = (wid >> 1) * 64;
    int n0 = (wid & 1) * 64;

    const __nv_bfloat16* srcs[4] = {Ahi, Alo, Bhi, Blo};

    float d[4][8][4];
    #pragma unroll
    for (int i = 0; i < 4; i++)
        #pragma unroll
        for (int j = 0; j < 8; j++)
            #pragma unroll
            for (int k = 0; k < 4; k++) d[i][j][k] = 0.f;

    auto load_chunk = [&](uint32_t st, int kc) {
        long long ko = (long long)kc * 16;
        #pragma unroll
        for (int i = 0; i < 8; i++) {
            int idx = tid + i*128;             // 0..1023
            int t = idx >> 8;
            if (diag && t >= 2) continue;
            int row = (idx >> 1) & 127, h = idx & 1;
            const __nv_bfloat16* src = srcs[t] + (long long)row*((t < 2) ? pa : pb) + ko + h*8;
            cp16(st + t*TILE16 + row*SP16 + h*16, src);
        }
        cp_commit();
    };

    load_chunk(sbase, 0);

    int arow = lane & 15;
    int acol = (lane >> 4) * 16;
    int bro = ((lane >> 4) & 1)*8 + (lane & 7);
    int bby = ((lane >> 3) & 1) * 16;

    for (int c = 0; c < nchunks; c++) {
        int s = c & 1;
        if (c + 1 < nchunks) {
            load_chunk(sbase + (s^1)*STAGE16, c+1);
            asm volatile("cp.async.wait_group 1;");
        } else {
            asm volatile("cp.async.wait_group 0;");
        }
        __syncthreads();

        uint32_t stA = sbase + s*STAGE16;
        uint32_t stB = stA + (diag ? 0 : 2*TILE16);

        uint32_t aHi[4][4], aLo[4][4], bHi[8][2], bLo[8][2];
        #pragma unroll
        for (int mf = 0; mf < 4; mf++) {
            uint32_t addr = stA + (m0 + mf*16 + arow)*SP16 + acol;
            ldmat4(aHi[mf], addr);
            ldmat4(aLo[mf], addr + TILE16);
        }
        #pragma unroll
        for (int p = 0; p < 4; p++) {
            uint32_t addr = stB + (n0 + p*16 + bro)*SP16 + bby;
            ldmat4(bHi[p*2], addr);
            ldmat4(bLo[p*2], addr + TILE16);
        }
        #pragma unroll
        for (int mf = 0; mf < 4; mf++)
            #pragma unroll
            for (int nf = 0; nf < 8; nf++)
                mma16816(d[mf][nf], aHi[mf], bHi[nf]);
        #pragma unroll
        for (int mf = 0; mf < 4; mf++)
            #pragma unroll
            for (int nf = 0; nf < 8; nf++)
                mma16816(d[mf][nf], aHi[mf], bLo[nf]);
        #pragma unroll
        for (int mf = 0; mf < 4; mf++)
            #pragma unroll
            for (int nf = 0; nf < 8; nf++)
                mma16816(d[mf][nf], aLo[mf], bHi[nf]);
        __syncthreads();
    }

    int rr = lane >> 2, cc = (lane & 3) * 2;
    #pragma unroll
    for (int mf = 0; mf < 4; mf++)
        #pragma unroll
        for (int nf = 0; nf < 8; nf++) {
            long long r0 = (long long)(m0 + mf*16 + rr) * ldo + n0 + nf*8 + cc;
            long long r1 = r0 + 8*ldo;
            out[r0]   = d[mf][nf][0];
            out[r0+1] = d[mf][nf][1];
            out[r1]   = d[mf][nf][2];
            out[r1+1] = d[mf][nf][3];
        }
}

// gram: K = 16384 = 1024 chunks of 16; 7 splits: split0 = 148, splits 1..6 = 146
__global__ void __launch_bounds__(128,2) mma_gram_kernel(
    const __nv_bfloat16* __restrict__ Zhi, const __nv_bfloat16* __restrict__ Zlo,
    float* __restrict__ part)
{
    int tile = blockIdx.x, split = blockIdx.y, b = blockIdx.z;
    int koff = (split == 0) ? 0 : 16*(146*split + 2);
    int nch  = (split == 0) ? 148 : 146;
    int diag = (c_tr0[tile] == c_tc0[tile]) ? 1 : 0;
    long long ab = ((long long)(b*1152 + c_tr0[tile]))*HWX + koff;
    long long bb = ((long long)(b*1152 + c_tc0[tile]))*HWX + koff;
    float* out = part + (((long long)((b*21 + tile)*7 + split)) << 14);
    mma_core(Zhi+ab, Zlo+ab, Zhi+bb, Zlo+bb, HWX, HWX, nch, out, 128, diag);
}

// ---------------- mma_y: NN GEMM, B k-major + trans-ldmatrix ----------------
#define Y_BPITCH 272                 // 128 bf16 (256B) + 16 pad
#define Y_BTILE  (16*Y_BPITCH)       // 4352
#define Y_BOFF   (2*TILE16)          // 12288
#define Y_STAGE  (2*TILE16 + 2*Y_BTILE)  // 20992
#define Y_DSMEM  (2*Y_STAGE)             // 41984 -> 2 CTAs/SM

__global__ void __launch_bounds__(128,2) mma_y_kernel(
    const __nv_bfloat16* __restrict__ Whi, const __nv_bfloat16* __restrict__ Wlo,
    const __nv_bfloat16* __restrict__ Zhi, const __nv_bfloat16* __restrict__ Zlo,
    float* __restrict__ y)
{
    extern __shared__ char dyn[];
    uint32_t sbase = smem_u32(dyn);
    int n0g = blockIdx.x * 128, m0g = blockIdx.y * 128, b = blockIdx.z;
    const __nv_bfloat16* Ahi = Whi + (long long)(b*256 + m0g) * 1024;
    const __nv_bfloat16* Alo = Wlo + (long long)(b*256 + m0g) * 1024;
    const __nv_bfloat16* Bhi = Zhi + (long long)(b*1152)*HWX + n0g;
    const __nv_bfloat16* Blo = Zlo + (long long)(b*1152)*HWX + n0g;
    float* out = y + (long long)(b*256 + m0g)*HWX + n0g;

    int tid = threadIdx.x, lane = tid & 31, wid = tid >> 5;
    int m0 = (wid >> 1) * 64;
    int n0 = (wid & 1) * 64;

    float d[4][8][4];
    #pragma unroll
    for (int i = 0; i < 4; i++)
        #pragma unroll
        for (int j = 0; j < 8; j++)
            #pragma unroll
            for (int k = 0; k < 4; k++) d[i][j][k] = 0.f;

    auto load_chunk = [&](uint32_t st, int kc) {
        long long ko = (long long)kc * 16;
        #pragma unroll
        for (int i = 0; i < 4; i++) {              // A: 512 cp16
            int idx = tid + i*128;
            int t = idx >> 8, row = (idx >> 1) & 127, h = idx & 1;
            const __nv_bfloat16* src = (t ? Alo : Ahi) + (long long)row*1024 + ko + h*8;
            cp16(st + t*TILE16 + row*SP16 + h*16, src);
        }
        #pragma unroll
        for (int i = 0; i < 4; i++) {              // B: 512 cp16
            int idx = tid + i*128;
            int t = idx >> 8, row = (idx >> 4) & 15, c16 = idx & 15;
            const __nv_bfloat16* src = (t ? Blo : Bhi) + (ko + row)*(long long)HWX + c16*8;
            cp16(st + Y_BOFF + t*Y_BTILE + row*Y_BPITCH + c16*16, src);
        }
        cp_commit();
    };

    load_chunk(sbase, 0);

    int arow = lane & 15;
    int acol = (lane >> 4) * 16;
    int bk = lane & 15;
    int bh = (lane >> 4) * 8;

    const int nch = 64;
    for (int c = 0; c < nch; c++) {
        int s = c & 1;
        if (c + 1 < nch) {
            load_chunk(sbase + (s^1)*Y_STAGE, c+1);
            asm volatile("cp.async.wait_group 1;");
        } else {
            asm volatile("cp.async.wait_group 0;");
        }
        __syncthreads();

        uint32_t stA = sbase + s*Y_STAGE;

        uint32_t aHi[4][4], aLo[4][4], bHi[8][2], bLo[8][2];
        #pragma unroll
        for (int mf = 0; mf < 4; mf++) {
            uint32_t addr = stA + (m0 + mf*16 + arow)*SP16 + acol;
            ldmat4(aHi[mf], addr);
            ldmat4(aLo[mf], addr + TILE16);
        }
        #pragma unroll
        for (int p = 0; p < 4; p++) {
            uint32_t addr = stA + Y_BOFF + bk*Y_BPITCH + (n0 + p*16 + bh)*2;
            ldmat4_trans(bHi[p*2], addr);
            ldmat4_trans(bLo[p*2], addr + Y_BTILE);
        }
        #pragma unroll
        for (int mf = 0; mf < 4; mf++)
            #pragma unroll
            for (int nf = 0; nf < 8; nf++)
                mma16816(d[mf][nf], aHi[mf], bHi[nf]);
        #pragma unroll
        for (int mf = 0; mf < 4; mf++)
            #pragma unroll
            for (int nf = 0; nf < 8; nf++)
                mma16816(d[mf][nf], aHi[mf], bLo[nf]);
        #pragma unroll
        for (int mf = 0; mf < 4; mf++)
            #pragma unroll
            for (int nf = 0; nf < 8; nf++)
                mma16816(d[mf][nf], aLo[mf], bHi[nf]);
        __syncthreads();
    }

    int rr = lane >> 2, cc = (lane & 3) * 2;
    #pragma unroll
    for (int mf = 0; mf < 4; mf++)
        #pragma unroll
        for (int nf = 0; nf < 8; nf++) {
            long long r0 = (long long)(m0 + mf*16 + rr) * HWX + n0 + nf*8 + cc;
            long long r1 = r0 + 8*HWX;
            out[r0]   = d[mf][nf][0];
            out[r0+1] = d[mf][nf][1];
            out[r1]   = d[mf][nf][2];
            out[r1+1] = d[mf][nf][3];
        }
}

// ---------------- kernel 1: dilated conv + relu + 1x1 + softmax -> sw ------
__global__ void __launch_bounds__(128) convsw_kernel(
    const float* __restrict__ cen, const float* __restrict__ w1a,
    const float* __restrict__ b1a, const float* __restrict__ w2a,
    const float* __restrict__ b2a, const float* __restrict__ sumwa,
    float* __restrict__ swa)
{
    int ish = blockIdx.y;
    int d = 1 << ish;
    const float* w1 = w1a + ish*9216;
    const float* b1 = b1a + ish*32;
    const float* w2 = w2a + ish*256;
    const float* b2 = b2a + ish*8;
    const float* sumw = sumwa + ish*2;
    float* sw = swa + (long long)ish*Bb*8*HWX;

    __shared__ float s_w1[32*9*32];
    __shared__ float s_w2[8*32];
    __shared__ float s_b1[32];
    __shared__ float s_b2[8];
    int tid = threadIdx.x;
    for (int idx = tid; idx < 9216; idx += 128) {
        int o = idx / 288; int rem = idx % 288; int ci = rem / 9; int t = rem % 9;
        s_w1[(ci*9 + t)*32 + o] = w1[idx];
    }
    for (int idx = tid; idx < 256; idx += 128) s_w2[idx] = w2[idx];
    if (tid < 32) s_b1[tid] = b1[tid];
    if (tid < 8)  s_b2[tid] = b2[tid];
    __syncthreads();

    int b = blockIdx.x >> 7;
    int y = blockIdx.x & 127;
    int x = tid;

    float acc[32];
    #pragma unroll
    for (int o = 0; o < 32; o++) acc[o] = 0.f;

    const float* cb = cen + ((long long)b*32) * HWX;
    for (int ci = 0; ci < 32; ci++) {
        float v[9];
        #pragma unroll
        for (int ky = 0; ky < 3; ky++) {
            int ry = y + (ky-1)*d;
            bool yok = (ry >= 0 && ry < Hd);
            #pragma unroll
            for (int kx = 0; kx < 3; kx++) {
                int cx = x + (kx-1)*d;
                bool ok = yok && (cx >= 0) && (cx < Wd);
                v[ky*3+kx] = ok ? cb[ci*HWX + ry*Wd + cx] : 0.f;
            }
        }
        #pragma unroll
        for (int t = 0; t < 9; t++) {
            const float4* wp = (const float4*)&s_w1[(ci*9+t)*32];
            float vv = v[t];
            #pragma unroll
            for (int o4 = 0; o4 < 8; o4++) {
                float4 w = wp[o4];
                acc[o4*4+0] += vv*w.x; acc[o4*4+1] += vv*w.y;
                acc[o4*4+2] += vv*w.z; acc[o4*4+3] += vv*w.w;
            }
        }
    }

    float lg[8];
    #pragma unroll
    for (int k = 0; k < 8; k++) lg[k] = s_b2[k];
    #pragma unroll
    for (int o = 0; o < 32; o++) {
        float h = acc[o] + s_b1[o]; h = h > 0.f ? h : 0.f;
        #pragma unroll
        for (int k = 0; k < 8; k++) lg[k] += h * s_w2[k*32 + o];
    }
    float mx = lg[0];
    #pragma unroll
    for (int k = 1; k < 8; k++) mx = fmaxf(mx, lg[k]);
    float e[8], se = 0.f;
    #pragma unroll
    for (int k = 0; k < 8; k++) { e[k] = expf(lg[k]-mx); se += e[k]; }

    float a0 = sumw[0], a1 = sumw[1];
    float am = fmaxf(a0, a1);
    float e0 = expf(a0-am), e1 = expf(a1-am);
    float g0 = e0/(e0+e1);
    float scale = g0 / se;

    long long pix = (long long)y*Wd + x;
    #pragma unroll
    for (int k = 0; k < 8; k++)
        sw[(((long long)(b*8+k)) << 14) + pix] = e[k]*scale;
}

// ---------------- kernel 2: neighbors -> Z (bf16 hi/lo), all shifts --------
__global__ void __launch_bounds__(256) sur_kernel(
    const float* __restrict__ cen, const float* __restrict__ swa,
    const float* __restrict__ sumwa,
    __nv_bfloat16* __restrict__ Zhi, __nv_bfloat16* __restrict__ Zlo)
{
    int ik = blockIdx.y;
    int d = 1 << ik;
    const float* sw = swa + (long long)ik*Bb*8*HWX;
    const float* sumw = sumwa + ik*2;

    int t = blockIdx.x * 256 + threadIdx.x;
    int b = t >> 19;
    int c = (t >> 14) & 31;
    int s = t & 16383;
    int y = s >> 7, x = s & 127;

    float a0 = sumw[0], a1 = sumw[1];
    float am = fmaxf(a0, a1);
    float e0 = expf(a0-am), e1 = expf(a1-am);
    float g0 = e0/(e0+e1), g1 = e1/(e0+e1);

    int ym = y-d; ym = ym < 0 ? -ym : ym;
    int yp = y+d; yp = yp > 127 ? 254 - yp : yp;
    int xm = x-d; xm = xm < 0 ? -xm : xm;
    int xp = x+d; xp = xp > 127 ? 254 - xp : xp;

    const float* base = cen + (((long long)(b*32 + c)) << 14);
    float nb[8];
    nb[0]=base[ym*128+xm]; nb[1]=base[ym*128+x]; nb[2]=base[ym*128+xp];
    nb[3]=base[y *128+xm];                       nb[4]=base[y *128+xp];
    nb[5]=base[yp*128+xm]; nb[6]=base[yp*128+x]; nb[7]=base[yp*128+xp];
    float cv = base[y*128+x];

    float sumx = cv * g1;
    float mean = 0.f;
    #pragma unroll
    for (int k = 0; k < 8; k++) {
        float swv = sw[(((long long)(b*8+k)) << 14) + s];
        sumx += nb[k]*swv;
        mean += nb[k];
    }
    mean *= 0.125f;
    long long zb = (long long)b*1152*HWX;

    float vc = mean*g0 + cv*g1;
    {
        __nv_bfloat16 h = __float2bfloat16(vc);
        __nv_bfloat16 l = __float2bfloat16(vc - __bfloat162float(h));
        long long idx = zb + (long long)(1024 + ik*32 + c)*HWX + s;
        Zhi[idx] = h; Zlo[idx] = l;
    }
    #pragma unroll
    for (int k = 0; k < 8; k++) {
        float v = nb[k] - sumx;
        __nv_bfloat16 h = __float2bfloat16(v);
        __nv_bfloat16 l = __float2bfloat16(v - __bfloat162float(h));
        long long idx = zb + (long long)(ik*256 + k*32 + c)*HWX + s;
        Zhi[idx] = h; Zlo[idx] = l;
    }
}

// ---------------- fp32 -> bf16 hi/lo ----------------------------------------
__global__ void __launch_bounds__(256) tobf16_kernel(
    const float* __restrict__ X, __nv_bfloat16* __restrict__ hi,
    __nv_bfloat16* __restrict__ lo, int n)
{
    int i = blockIdx.x*256 + threadIdx.x;
    if (i < n) {
        float v = X[i];
        __nv_bfloat16 h = __float2bfloat16(v);
        __nv_bfloat16 l = __float2bfloat16(v - __bfloat162float(h));
        hi[i] = h; lo[i] = l;
    }
}

// ---------------- gram reduce + scatter -------------------------------------
__global__ void __launch_bounds__(256) gramred_kernel(
    const float* __restrict__ part, float* __restrict__ Gq,
    float* __restrict__ M, float* __restrict__ Gc)
{
    int idx = blockIdx.x*256 + threadIdx.x;
    int b = idx / (21*16384);
    int rem = idx - b*21*16384;
    int tile = rem >> 14;
    int e = rem & 16383;
    float v = 0.f;
    const float* p = part + (((long long)(b*21 + tile)*7) << 14) + e;
    #pragma unroll
    for (int s = 0; s < 7; s++) v += p[(long long)s << 14];
    int r = e >> 7, c = e & 127;
    if (tile < 12) {
        int ik = tile/3, sub = tile - ik*3;
        int gr = (sub==2 ? 128:0) + r;
        int gc = (sub==0 ? 0:128) + c;
        float* G = Gq + (long long)(b*4+ik)*65536;
        G[gr*256 + gc] = v;
        if (sub == 1) G[gc*256 + gr] = v;
    } else if (tile < 20) {
        int cb = tile - 12;
        M[(long long)b*131072 + r*1024 + cb*128 + c] = v;
    } else {
        Gc[(long long)b*16384 + r*128 + c] = v;
    }
}

// ---------------- kn = sqrt(diag(kw G kw^T)) — smem-tiled -------------------
#define KN_PITCH 260
#define KN_SMEM  (2*32*KN_PITCH*4)

__global__ void __launch_bounds__(256) kn_kernel(
    const float* __restrict__ kw, const float* __restrict__ Gq,
    float* __restrict__ kn)
{
    extern __shared__ float kdyn[];
    float* Wsh = kdyn;
    float* Gs  = kdyn + 32*KN_PITCH;
    int z = blockIdx.y;
    int ik = z & 3;
    int rbase = blockIdx.x * 32;
    const float* W = kw + (long long)ik*512*256 + (long long)rbase*256;
    const float* G = Gq + (long long)z*65536;
    int tid = threadIdx.x;
    for (int idx = tid; idx < 8192; idx += 256) {
        int r = idx >> 8, i = idx & 255;
        Wsh[r*KN_PITCH + i] = W[r*256 + i];
    }
    __syncthreads();
    int r = tid >> 3, seg = tid & 7;
    float acc = 0.f;
    for (int jt = 0; jt < 8; jt++) {
        for (int idx = tid; idx < 8192; idx += 256) {
            int jj = idx >> 8, i = idx & 255;
            Gs[jj*KN_PITCH + i] = G[(jt*32 + jj)*256 + i];
        }
        __syncthreads();
        #pragma unroll 4
        for (int jj = 0; jj < 32; jj++) {
            const float* gr = &Gs[jj*KN_PITCH + seg*32];
            const float* wr = &Wsh[r*KN_PITCH + seg*32];
            float dd = 0.f;
            #pragma unroll
            for (int ii = 0; ii < 32; ii++) dd += gr[ii]*wr[ii];
            acc += Wsh[r*KN_PITCH + jt*32 + jj] * dd;
        }
        __syncthreads();
    }
    acc += __shfl_xor_sync(0xffffffffu, acc, 4);
    acc += __shfl_xor_sync(0xffffffffu, acc, 2);
    acc += __shfl_xor_sync(0xffffffffu, acc, 1);
    if (seg == 0)
        kn[z*512 + rbase + r] = fmaxf(sqrtf(fmaxf(acc, 0.f)), 1e-12f);
}

// ---------------- qn = sqrt(diag(qw Gc qw^T)) -------------------------------
__global__ void __launch_bounds__(64) qn_kernel(
    const float* __restrict__ qw, const float* __restrict__ Gc,
    float* __restrict__ qn)
{
    int z = blockIdx.x;
    int b = z >> 2, iq = z & 3;
    __shared__ float Gs[32*33];
    int tid = threadIdx.x;
    for (int idx = tid; idx < 1024; idx += 64) {
        int r = idx >> 5, c = idx & 31;
        Gs[r*33 + c] = Gc[(long long)b*16384 + (iq*32+r)*128 + iq*32 + c];
    }
    __syncthreads();
    const float* w = qw + iq*2048 + tid*32;
    float wr[32];
    #pragma unroll
    for (int i = 0; i < 32; i++) wr[i] = w[i];
    float acc = 0.f;
    #pragma unroll
    for (int i = 0; i < 32; i++) {
        float s = 0.f;
        #pragma unroll
        for (int j = 0; j < 32; j++) s += Gs[i*33+j]*wr[j];
        acc += wr[i]*s;
    }
    qn[z*64 + tid] = fmaxf(sqrtf(fmaxf(acc, 0.f)), 1e-12f);
}

// ---------------- score assembly: S = qw M kw^T, scaled ---------------------
__global__ void __launch_bounds__(128) scoreasm_kernel(
    const float* __restrict__ qw, const float* __restrict__ kw,
    const float* __restrict__ M,  const float* __restrict__ qn,
    const float* __restrict__ kn, float* __restrict__ score)
{
    int bid = blockIdx.x;
    int b  = bid >> 6;
    int n  = (bid >> 4) & 3;
    int iq = (bid >> 2) & 3;
    int ik = bid & 3;
    int tid = threadIdx.x;

    __shared__ float qws[16*32];
    __shared__ float P[16*256];
    __shared__ float buf[32*132];

    for (int idx = tid; idx < 512; idx += 128) {
        int o = idx >> 5, ch = idx & 31;
        qws[o*32 + ch] = qw[iq*2048 + (16*n + o)*32 + ch];
    }
    __syncthreads();

    const float* Mb = M + (long long)b*131072 + (long long)(iq*32)*1024 + ik*256;
    for (int h = 0; h < 2; h++) {
        for (int idx = tid; idx < 4096; idx += 128) {
            int ch = idx >> 7, cl = idx & 127;
            buf[ch*132 + cl] = Mb[(long long)ch*1024 + h*128 + cl];
        }
        __syncthreads();
        int o = tid >> 3, cg = tid & 7;
        #pragma unroll
        for (int j = 0; j < 16; j++) {
            int cl = cg*16 + j;
            float s = 0.f;
            #pragma unroll
            for (int ch = 0; ch < 32; ch++) s += qws[o*32+ch]*buf[ch*132+cl];
            P[o*256 + h*128 + cl] = s;
        }
        __syncthreads();
    }

    float acc[16] = {};
    const float* Kw = kw + (long long)ik*512*256 + (long long)(128*n)*256;
    for (int h2 = 0; h2 < 8; h2++) {
        for (int i = 0; i < 32; i++) {
            int idx = i*128 + tid;
            int row = idx >> 5, j = idx & 31;
            buf[j*132 + row] = Kw[(long long)row*256 + h2*32 + j];
        }
        __syncthreads();
        #pragma unroll
        for (int j = 0; j < 32; j++) {
            float kv = buf[j*132 + tid];
            #pragma unroll
            for (int o = 0; o < 16; o++)
                acc[o] += P[o*256 + h2*32 + j] * kv;
        }
        __syncthreads();
    }

    float knv = kn[(b*4+ik)*512 + 128*n + tid];
    #pragma unroll
    for (int o = 0; o < 16; o++) {
        float qnv = qn[(b*4+iq)*64 + 16*n + o];
        float v = acc[o] / (128.f * qnv * knv);
        int q = 4*o + iq, k = 4*tid + ik;
        score[((long long)(b*4+n)*64 + q)*512 + k] = v;
    }
}

// ---------------- InstanceNorm + softmax (in place) -------------------------
__global__ void __launch_bounds__(1024) insoftmax_kernel(float* __restrict__ score)
{
    int bn = blockIdx.x;
    int tid = threadIdx.x;
    float s1 = 0.f, s2 = 0.f;
    for (int e = tid; e < 32768; e += 1024) {
        float v = score[((long long)bn << 15) + e];
        s1 += v; s2 += v*v;
    }
    __shared__ float r1[32], r2[32];
    s1 = warpsum(s1); s2 = warpsum(s2);
    int w = tid >> 5, l = tid & 31;
    if (l == 0) { r1[w] = s1; r2[w] = s2; }
    __syncthreads();
    __shared__ float smu, srstd;
    if (tid == 0) {
        float t1 = 0.f, t2 = 0.f;
        #pragma unroll
        for (int i = 0; i < 32; i++) { t1 += r1[i]; t2 += r2[i]; }
        float mu  = t1 / 32768.f;
        float var = fmaxf(t2/32768.f - mu*mu, 0.f);
        smu = mu; srstd = rsqrtf(var + 1e-5f);
    }
    __syncthreads();
    float mu = smu, rstd = srstd;
    #pragma unroll
    for (int qq = 0; qq < 2; qq++) {
        int q = w*2 + qq;
        float v[16];
        float mx = -1e30f;
        #pragma unroll
        for (int j = 0; j < 16; j++) {
            v[j] = (score[((long long)bn << 15) + q*512 + l + j*32] - mu) * rstd;
            mx = fmaxf(mx, v[j]);
        }
        #pragma unroll
        for (int o = 16; o > 0; o >>= 1) mx = fmaxf(mx, __shfl_xor_sync(~0u, mx, o));
        float sum = 0.f;
        #pragma unroll
        for (int j = 0; j < 16; j++) { v[j] = expf(v[j]-mx); sum += v[j]; }
        sum = warpsum(sum);
        float invs = 1.f / sum;
        #pragma unroll
        for (int j = 0; j < 16; j++)
            score[((long long)bn << 15) + q*512 + l + j*32] = v[j]*invs;
    }
}

// ---------------- ucat ------------------------------------------------------
__global__ void __launch_bounds__(256) ucat_kernel(
    const float* __restrict__ attn, const float* __restrict__ vw,
    float* __restrict__ ucat)
{
    int bid = blockIdx.x;
    int b  = bid >> 4;
    int ik = (bid >> 2) & 3;
    int n  = bid & 3;
    int tid = threadIdx.x;

    __shared__ float A[64*128];
    for (int idx = tid; idx < 8192; idx += 256) {
        int q = idx >> 7, cp = idx & 127;
        A[idx] = attn[((long long)(b*4+n)*64 + q)*512 + 4*cp + ik];
    }
    __syncthreads();

    float acc[64] = {};
    const float* V = vw + (long long)ik*512*256 + (long long)(128*n)*256;
    for (int cp = 0; cp < 128; cp++) {
        float wv = V[(long long)cp*256 + tid];
        #pragma unroll
        for (int q = 0; q < 64; q++)
            acc[q] += A[q*128 + cp] * wv;
    }
    float* uo = ucat + (long long)b*262144 + (long long)(n*64)*1024 + ik*256 + tid;
    #pragma unroll
    for (int q = 0; q < 64; q++)
        uo[(long long)q*1024] = acc[q];
}

// ---------------- generic NN SGEMM (wcat only) ------------------------------
__global__ void __launch_bounds__(256) sgemm_nn(
    const float* __restrict__ A, const float* __restrict__ B, float* __restrict__ C,
    int M, int N, int K,
    long long sA, long long sB, long long sC,
    int rowmul, int rowadd)
{
    A += (long long)blockIdx.z * sA;
    B += (long long)blockIdx.z * sB;
    C += (long long)blockIdx.z * sC;
    int m0 = blockIdx.y * 64;
    int n0 = blockIdx.x * 128;
    __shared__ float As[16][64];
    __shared__ float Bs[16][128];
    int tid = threadIdx.x;
    int tx = tid & 15, ty = tid >> 4;
    float acc[4][8] = {};
    int am = tid >> 2, ak = (tid & 3) * 4;

    for (int kt = 0; kt < K; kt += 16) {
        float4 av = *(const float4*)&A[(long long)(m0+am)*K + kt + ak];
        As[ak+0][am] = av.x; As[ak+1][am] = av.y;
        As[ak+2][am] = av.z; As[ak+3][am] = av.w;
        #pragma unroll
        for (int i = 0; i < 2; i++) {
            int idx = tid + i*256;
            int k = idx >> 5, n4 = idx & 31;
            *(float4*)&Bs[k][n4*4] = *(const float4*)&B[(long long)(kt+k)*N + n0 + n4*4];
        }
        __syncthreads();
        #pragma unroll
        for (int k = 0; k < 16; k++) {
            float4 a4 = *(const float4*)&As[k][ty*4];
            float4 b0 = *(const float4*)&Bs[k][tx*4];
            float4 b1 = *(const float4*)&Bs[k][64 + tx*4];
            float a[4]  = {a4.x,a4.y,a4.z,a4.w};
            float bb[8] = {b0.x,b0.y,b0.z,b0.w,b1.x,b1.y,b1.z,b1.w};
            #pragma unroll
            for (int i = 0; i < 4; i++)
                #pragma unroll
                for (int j = 0; j < 8; j++)
                    acc[i][j] += a[i]*bb[j];
        }
        __syncthreads();
    }
    #pragma unroll
    for (int i = 0; i < 4; i++) {
        long long r = (long long)((m0 + ty*4 + i) * rowmul + rowadd) * N;
        float4 c0 = make_float4(acc[i][0],acc[i][1],acc[i][2],acc[i][3]);
        float4 c1 = make_float4(acc[i][4],acc[i][5],acc[i][6],acc[i][7]);
        *(float4*)&C[r + n0 + tx*4]      = c0;
        *(float4*)&C[r + n0 + 64 + tx*4] = c1;
    }
}

// ---------------- BatchNorm stats + normalize/relu -------------------------
__global__ void __launch_bounds__(256) bnstats_kernel(
    const float* __restrict__ y, float* __restrict__ mv)
{
    int o = blockIdx.x;
    float s1 = 0.f, s2 = 0.f;
    for (int idx = threadIdx.x; idx < 8192; idx += 256) {
        int b = idx >> 12, s4 = idx & 4095;
        float4 v4 = *(const float4*)&y[(((long long)(b*256 + o)) << 14) + s4*4];
        s1 += v4.x + v4.y + v4.z + v4.w;
        s2 += v4.x*v4.x + v4.y*v4.y + v4.z*v4.z + v4.w*v4.w;
    }
    s1 = warpsum(s1); s2 = warpsum(s2);
    __shared__ float r1[8], r2[8];
    int w = threadIdx.x >> 5, l = threadIdx.x & 31;
    if (l == 0) { r1[w] = s1; r2[w] = s2; }
    __syncthreads();
    if (threadIdx.x == 0) {
        float t1 = 0.f, t2 = 0.f;
        #pragma unroll
        for (int i = 0; i < 8; i++) { t1 += r1[i]; t2 += r2[i]; }
        float mean = t1 / 32768.f;
        float var  = fmaxf(t2/32768.f - mean*mean, 0.f);
        mv[o*2]   = mean;
        mv[o*2+1] = rsqrtf(var + 1e-5f);
    }
}

__global__ void __launch_bounds__(256) bnrelu_kernel(
    const float* __restrict__ y, const float* __restrict__ mv,
    const float* __restrict__ gamma, const float* __restrict__ beta,
    float* __restrict__ out)
{
    long long t4 = (long long)blockIdx.x * 256 + threadIdx.x;
    int o = (int)((t4 >> 12) & 255);
    float mean = mv[o*2], rstd = mv[o*2+1];
    float ga = gamma[o], be = beta[o];
    float4 v = *(const float4*)&y[t4*4];
    v.x = fmaxf((v.x-mean)*rstd*ga + be, 0.f);
    v.y = fmaxf((v.y-mean)*rstd*ga + be, 0.f);
    v.z = fmaxf((v.z-mean)*rstd*ga + be, 0.f);
    v.w = fmaxf((v.w-mean)*rstd*ga + be, 0.f);
    *(float4*)&out[t4*4] = v;
}

// ---------------- host side -------------------------------------------------
extern "C" void kernel_launch(void* const* d_in, const int* in_sizes, int n_in,
                              void* d_out, int out_size)
{
    (void)in_sizes; (void)n_in; (void)out_size;
    const float* cen   = (const float*)d_in[0];
    const float* q_w   = (const float*)d_in[1];
    const float* k_w   = (const float*)d_in[2];
    const float* v_w   = (const float*)d_in[3];
    const float* sw1   = (const float*)d_in[4];
    const float* sb1   = (const float*)d_in[5];
    const float* sw2   = (const float*)d_in[6];
    const float* sb2   = (const float*)d_in[7];
    const float* sumw  = (const float*)d_in[8];
    const float* out_w = (const float*)d_in[9];
    const float* gamma = (const float*)d_in[10];
    const float* beta  = (const float*)d_in[11];
    float* out = (float*)d_out;

    float *p_sw,*p_part,*p_Gq,*p_M,*p_Gc,*p_kn,*p_qn,*p_score,*p_ucat,*p_wcat,*p_y,*p_bn;
    __nv_bfloat16 *p_Zhi,*p_Zlo,*p_whi,*p_wlo;
    cudaGetSymbolAddress((void**)&p_sw,   g_sw);
    cudaGetSymbolAddress((void**)&p_Zhi,  g_Zhi);
    cudaGetSymbolAddress((void**)&p_Zlo,  g_Zlo);
    cudaGetSymbolAddress((void**)&p_part, g_part);
    cudaGetSymbolAddress((void**)&p_Gq,   g_Gq);
    cudaGetSymbolAddress((void**)&p_M,    g_M);
    cudaGetSymbolAddress((void**)&p_Gc,   g_Gc);
    cudaGetSymbolAddress((void**)&p_kn,   g_kn);
    cudaGetSymbolAddress((void**)&p_qn,   g_qn);
    cudaGetSymbolAddress((void**)&p_score,g_score);
    cudaGetSymbolAddress((void**)&p_ucat, g_ucat);
    cudaGetSymbolAddress((void**)&p_wcat, g_wcat);
    cudaGetSymbolAddress((void**)&p_whi,  g_whi);
    cudaGetSymbolAddress((void**)&p_wlo,  g_wlo);
    cudaGetSymbolAddress((void**)&p_y,    g_y);
    cudaGetSymbolAddress((void**)&p_bn,   g_bn);

    cudaFuncSetAttribute(mma_gram_kernel, cudaFuncAttributeMaxDynamicSharedMemorySize, G_DSMEM);
    cudaFuncSetAttribute(mma_y_kernel,    cudaFuncAttributeMaxDynamicSharedMemorySize, Y_DSMEM);
    cudaFuncSetAttribute(kn_kernel,       cudaFuncAttributeMaxDynamicSharedMemorySize, KN_SMEM);

    convsw_kernel<<<dim3(Bb*Hd, 4), 128>>>(cen, sw1, sb1, sw2, sb2, sumw, p_sw);
    sur_kernel<<<dim3(4096, 4), 256>>>(cen, p_sw, sumw, p_Zhi, p_Zlo);
    mma_gram_kernel<<<dim3(21, 7, Bb), 128, G_DSMEM>>>(p_Zhi, p_Zlo, p_part);
    gramred_kernel<<<Bb*21*64, 256>>>(p_part, p_Gq, p_M, p_Gc);
    kn_kernel<<<dim3(16, Bb*4), 256, KN_SMEM>>>(k_w, p_Gq, p_kn);
    qn_kernel<<<Bb*4, 64>>>(q_w, p_Gc, p_qn);
    scoreasm_kernel<<<128, 128>>>(q_w, k_w, p_M, p_qn, p_kn, p_score);
    insoftmax_kernel<<<8, 1024>>>(p_score);
    ucat_kernel<<<Bb*16, 256>>>(p_score, v_w, p_ucat);
    sgemm_nn<<<dim3(8, 4, Bb), 256>>>(out_w, p_ucat, p_wcat, 256, 1024, 256,
                                      0LL, 262144LL, 262144LL, 1, 0);
    tobf16_kernel<<<2048, 256>>>(p_wcat, p_whi, p_wlo, Bb*256*1024);
    mma_y_kernel<<<dim3(128, 2, Bb), 128, Y_DSMEM>>>(p_whi, p_wlo, p_Zhi, p_Zlo, p_y);
    bnstats_kernel<<<256, 256>>>(p_y, p_bn);
    bnrelu_kernel<<<8192, 256>>>(p_y, p_bn, gamma, beta, out);
}

// round 16
// speedup vs baseline: 1.0156x; 1.0156x over previous
#include <cuda_runtime.h>
#include <cuda_bf16.h>
#include <math.h>
#include <stdint.h>

#define HWX 16384
#define Wd  128
#define Hd  128
#define Bb  2

// ---------------- device scratch (no runtime alloc allowed) ----------------
__device__ float g_sw  [4*Bb*8*HWX];
__device__ __nv_bfloat16 g_Zhi[Bb*1152*HWX];
__device__ __nv_bfloat16 g_Zlo[Bb*1152*HWX];
__device__ float g_part[Bb*21*8*16384];
__device__ float g_Gq  [Bb*4*256*256];
__device__ float g_M   [Bb*128*1024];
__device__ float g_Gc  [Bb*128*128];
__device__ float g_kn  [Bb*4*512];
__device__ float g_qn  [Bb*4*64];
__device__ float g_score[8*64*512];
__device__ float g_ucat[Bb*256*1024];
__device__ __nv_bfloat16 g_whi[Bb*256*1024];
__device__ __nv_bfloat16 g_wlo[Bb*256*1024];
__device__ float g_y   [Bb*256*HWX];
__device__ float g_bn  [512];

__constant__ int c_tr0[21] = {0,0,128, 256,256,384, 512,512,640, 768,768,896,
                              1024,1024,1024,1024,1024,1024,1024,1024, 1024};
__constant__ int c_tc0[21] = {0,128,128, 256,384,384, 512,640,640, 768,896,896,
                              0,128,256,384,512,640,768,896, 1024};

__device__ __forceinline__ float warpsum(float v) {
    #pragma unroll
    for (int o = 16; o > 0; o >>= 1) v += __shfl_xor_sync(0xffffffffu, v, o);
    return v;
}

// ====================== warp-MMA helpers (family-safe PTX) ==================
__device__ __forceinline__ uint32_t smem_u32(const void* p) {
    uint32_t a;
    asm("{ .reg .u64 t; cvta.to.shared.u64 t, %1; cvt.u32.u64 %0, t; }" : "=r"(a) : "l"(p));
    return a;
}
__device__ __forceinline__ void cp16(uint32_t dst, const void* src) {
    asm volatile("cp.async.cg.shared.global [%0], [%1], 16;" :: "r"(dst), "l"(src));
}
__device__ __forceinline__ void cp_commit() {
    asm volatile("cp.async.commit_group;");
}
__device__ __forceinline__ void ldmat4(uint32_t* r, uint32_t addr) {
    asm volatile("ldmatrix.sync.aligned.m8n8.x4.shared.b16 {%0,%1,%2,%3}, [%4];"
        : "=r"(r[0]),"=r"(r[1]),"=r"(r[2]),"=r"(r[3]) : "r"(addr));
}
__device__ __forceinline__ void ldmat2(uint32_t* r, uint32_t addr) {
    asm volatile("ldmatrix.sync.aligned.m8n8.x2.shared.b16 {%0,%1}, [%2];"
        : "=r"(r[0]),"=r"(r[1]) : "r"(addr));
}
__device__ __forceinline__ void ldmat2_trans(uint32_t* r, uint32_t addr) {
    asm volatile("ldmatrix.sync.aligned.m8n8.x2.trans.shared.b16 {%0,%1}, [%2];"
        : "=r"(r[0]),"=r"(r[1]) : "r"(addr));
}
__device__ __forceinline__ void mma16816(float* d, const uint32_t* a, const uint32_t* b) {
    asm volatile("mma.sync.aligned.m16n8k16.row.col.f32.bf16.bf16.f32 "
        "{%0,%1,%2,%3}, {%4,%5,%6,%7}, {%8,%9}, {%0,%1,%2,%3};"
        : "+f"(d[0]),"+f"(d[1]),"+f"(d[2]),"+f"(d[3])
        : "r"(a[0]),"r"(a[1]),"r"(a[2]),"r"(a[3]), "r"(b[0]),"r"(b[1]));
}

#define SPITCH_B 80                  // bytes per smem row (32 bf16 + 8 pad)
#define TILE_B   (128*SPITCH_B)      // 10240
#define STAGE_B  (4*TILE_B)          // 40960
#define DSMEM_BYTES (2*STAGE_B)      // 81920 -> 2 CTAs/SM

// ---------------- bf16-split warp-MMA core (NT, k-major; 2-stage) -----------
// pass-reordered mma: 16 independent accumulators between dependent ops
__device__ __forceinline__ void mma_core(
    const __nv_bfloat16* __restrict__ Ahi, const __nv_bfloat16* __restrict__ Alo,
    const __nv_bfloat16* __restrict__ Bhi, const __nv_bfloat16* __restrict__ Blo,
    long long pa, long long pb, int nchunks,
    float* __restrict__ out, long long ldo, int diag)
{
    extern __shared__ char dyn[];
    uint32_t sbase = smem_u32(dyn);
    int tid = threadIdx.x, lane = tid & 31, wid = tid >> 5;
    int m0 = (wid >> 2) * 64;
    int n0 = (wid & 3) * 32;

    const __nv_bfloat16* srcs[4] = {Ahi, Alo, Bhi, Blo};

    float d[4][4][4];
    #pragma unroll
    for (int i = 0; i < 4; i++)
        #pragma unroll
        for (int j = 0; j < 4; j++)
            #pragma unroll
            for (int k = 0; k < 4; k++) d[i][j][k] = 0.f;

    {
        #pragma unroll
        for (int i = 0; i < 8; i++) {
            int idx = tid + i*256;
            int t = idx >> 9;
            if (diag && t >= 2) continue;
            int rc = idx & 511, row = rc >> 2, c8 = rc & 3;
            const __nv_bfloat16* src = srcs[t] + (long long)row*((t < 2) ? pa : pb) + c8*8;
            cp16(sbase + t*TILE_B + row*SPITCH_B + c8*16, src);
        }
        cp_commit();
    }

    for (int c = 0; c < nchunks; c++) {
        int s = c & 1;
        if (c + 1 < nchunks) {
            long long koff = (long long)(c+1) * 32;
            uint32_t st = sbase + (s^1)*STAGE_B;
            #pragma unroll
            for (int i = 0; i < 8; i++) {
                int idx = tid + i*256;
                int t = idx >> 9;
                if (diag && t >= 2) continue;
                int rc = idx & 511, row = rc >> 2, c8 = rc & 3;
                const __nv_bfloat16* src = srcs[t] + (long long)row*((t < 2) ? pa : pb) + koff + c8*8;
                cp16(st + t*TILE_B + row*SPITCH_B + c8*16, src);
            }
            cp_commit();
            asm volatile("cp.async.wait_group 1;");
        } else {
            asm volatile("cp.async.wait_group 0;");
        }
        __syncthreads();

        uint32_t stA = sbase + s*STAGE_B;
        uint32_t stB = stA + (diag ? 0 : 2*TILE_B);
        int arow = lane & 15;
        int acol = ((lane >> 4) & 1) * 16;
        int brow = lane & 7;
        int bcol = ((lane >> 3) & 1) * 16;

        #pragma unroll
        for (int ks = 0; ks < 2; ks++) {
            uint32_t aHi[4][4], aLo[4][4], bHi[4][2], bLo[4][2];
            #pragma unroll
            for (int mf = 0; mf < 4; mf++) {
                uint32_t addr = stA + (m0 + mf*16 + arow)*SPITCH_B + ks*32 + acol;
                ldmat4(aHi[mf], addr);
                ldmat4(aLo[mf], addr + TILE_B);
            }
            #pragma unroll
            for (int nf = 0; nf < 4; nf++) {
                uint32_t addr = stB + (n0 + nf*8 + brow)*SPITCH_B + ks*32 + bcol;
                ldmat2(bHi[nf], addr);
                ldmat2(bLo[nf], addr + TILE_B);
            }
            #pragma unroll
            for (int mf = 0; mf < 4; mf++)
                #pragma unroll
                for (int nf = 0; nf < 4; nf++)
                    mma16816(d[mf][nf], aHi[mf], bHi[nf]);
            #pragma unroll
            for (int mf = 0; mf < 4; mf++)
                #pragma unroll
                for (int nf = 0; nf < 4; nf++)
                    mma16816(d[mf][nf], aHi[mf], bLo[nf]);
            #pragma unroll
            for (int mf = 0; mf < 4; mf++)
                #pragma unroll
                for (int nf = 0; nf < 4; nf++)
                    mma16816(d[mf][nf], aLo[mf], bHi[nf]);
        }
        __syncthreads();
    }

    int rr = lane >> 2, cc = (lane & 3) * 2;
    #pragma unroll
    for (int mf = 0; mf < 4; mf++)
        #pragma unroll
        for (int nf = 0; nf < 4; nf++) {
            long long r0 = (long long)(m0 + mf*16 + rr) * ldo + n0 + nf*8 + cc;
            long long r1 = r0 + 8*ldo;
            out[r0]   = d[mf][nf][0];
            out[r0+1] = d[mf][nf][1];
            out[r1]   = d[mf][nf][2];
            out[r1+1] = d[mf][nf][3];
        }
}

// gram: K = 16384 = 512 chunks of 32; 7 splits: split0 = 74 chunks, splits 1..6 = 73
__global__ void __launch_bounds__(256,2) mma_gram_kernel(
    const __nv_bfloat16* __restrict__ Zhi, const __nv_bfloat16* __restrict__ Zlo,
    float* __restrict__ part)
{
    int tile = blockIdx.x, split = blockIdx.y, b = blockIdx.z;
    int koff = (split == 0) ? 0 : 32*(73*split + 1);
    int nch  = (split == 0) ? 74 : 73;
    int diag = (c_tr0[tile] == c_tc0[tile]) ? 1 : 0;
    long long ab = ((long long)(b*1152 + c_tr0[tile]))*HWX + koff;
    long long bb = ((long long)(b*1152 + c_tc0[tile]))*HWX + koff;
    float* out = part + (((long long)((b*21 + tile)*7 + split)) << 14);
    mma_core(Zhi+ab, Zlo+ab, Zhi+bb, Zlo+bb, HWX, HWX, nch, out, 128, diag);
}

// ---------------- mma_y: NN GEMM, B loaded k-major + trans-ldmatrix ---------
#define Y_APITCH 80
#define Y_ATILE  (128*Y_APITCH)          // 10240
#define Y_BPITCH 272                     // 128 bf16 (256B) + 16 pad
#define Y_BTILE  (32*Y_BPITCH)           // 8704
#define Y_BOFF   (2*Y_ATILE)             // 20480
#define Y_STAGE  (2*Y_ATILE + 2*Y_BTILE) // 37888
#define Y_DSMEM  (2*Y_STAGE)             // 75776

__global__ void __launch_bounds__(256,2) mma_y_kernel(
    const __nv_bfloat16* __restrict__ Whi, const __nv_bfloat16* __restrict__ Wlo,
    const __nv_bfloat16* __restrict__ Zhi, const __nv_bfloat16* __restrict__ Zlo,
    float* __restrict__ y)
{
    extern __shared__ char dyn[];
    uint32_t sbase = smem_u32(dyn);
    int n0g = blockIdx.x * 128, m0g = blockIdx.y * 128, b = blockIdx.z;
    const __nv_bfloat16* Ahi = Whi + (long long)(b*256 + m0g) * 1024;
    const __nv_bfloat16* Alo = Wlo + (long long)(b*256 + m0g) * 1024;
    const __nv_bfloat16* Bhi = Zhi + (long long)(b*1152)*HWX + n0g;
    const __nv_bfloat16* Blo = Zlo + (long long)(b*1152)*HWX + n0g;
    float* out = y + (long long)(b*256 + m0g)*HWX + n0g;

    int tid = threadIdx.x, lane = tid & 31, wid = tid >> 5;
    int m0 = (wid >> 2) * 64;
    int n0 = (wid & 3) * 32;

    float d[4][4][4];
    #pragma unroll
    for (int i = 0; i < 4; i++)
        #pragma unroll
        for (int j = 0; j < 4; j++)
            #pragma unroll
            for (int k = 0; k < 4; k++) d[i][j][k] = 0.f;

    auto load_chunk = [&](uint32_t st, int kc) {
        long long koff = (long long)kc * 32;
        #pragma unroll
        for (int i = 0; i < 4; i++) {
            int idx = tid + i*256;
            int t = idx >> 9, rc = idx & 511, row = rc >> 2, c8 = rc & 3;
            const __nv_bfloat16* src = (t ? Alo : Ahi) + (long long)row*1024 + koff + c8*8;
            cp16(st + t*Y_ATILE + row*Y_APITCH + c8*16, src);
        }
        #pragma unroll
        for (int i = 0; i < 4; i++) {
            int idx = tid + i*256;
            int t = idx >> 9, rc = idx & 511, krow = rc >> 4, c16 = rc & 15;
            const __nv_bfloat16* src = (t ? Blo : Bhi) + (koff + krow)*(long long)HWX + c16*8;
            cp16(st + Y_BOFF + t*Y_BTILE + krow*Y_BPITCH + c16*16, src);
        }
        cp_commit();
    };

    load_chunk(sbase, 0);

    const int nchunks = 32;
    for (int c = 0; c < nchunks; c++) {
        int s = c & 1;
        if (c + 1 < nchunks) {
            load_chunk(sbase + (s^1)*Y_STAGE, c+1);
            asm volatile("cp.async.wait_group 1;");
        } else {
            asm volatile("cp.async.wait_group 0;");
        }
        __syncthreads();

        uint32_t stA = sbase + s*Y_STAGE;
        int arow = lane & 15;
        int acol = ((lane >> 4) & 1) * 16;
        int bk = lane & 15;

        #pragma unroll
        for (int ks = 0; ks < 2; ks++) {
            uint32_t aHi[4][4], aLo[4][4], bHi[4][2], bLo[4][2];
            #pragma unroll
            for (int mf = 0; mf < 4; mf++) {
                uint32_t addr = stA + (m0 + mf*16 + arow)*Y_APITCH + ks*32 + acol;
                ldmat4(aHi[mf], addr);
                ldmat4(aLo[mf], addr + Y_ATILE);
            }
            #pragma unroll
            for (int nf = 0; nf < 4; nf++) {
                uint32_t addr = stA + Y_BOFF + (ks*16 + bk)*Y_BPITCH + (n0 + nf*8)*2;
                ldmat2_trans(bHi[nf], addr);
                ldmat2_trans(bLo[nf], addr + Y_BTILE);
            }
            #pragma unroll
            for (int mf = 0; mf < 4; mf++)
                #pragma unroll
                for (int nf = 0; nf < 4; nf++)
                    mma16816(d[mf][nf], aHi[mf], bHi[nf]);
            #pragma unroll
            for (int mf = 0; mf < 4; mf++)
                #pragma unroll
                for (int nf = 0; nf < 4; nf++)
                    mma16816(d[mf][nf], aHi[mf], bLo[nf]);
            #pragma unroll
            for (int mf = 0; mf < 4; mf++)
                #pragma unroll
                for (int nf = 0; nf < 4; nf++)
                    mma16816(d[mf][nf], aLo[mf], bHi[nf]);
        }
        __syncthreads();
    }

    int rr = lane >> 2, cc = (lane & 3) * 2;
    #pragma unroll
    for (int mf = 0; mf < 4; mf++)
        #pragma unroll
        for (int nf = 0; nf < 4; nf++) {
            long long r0 = (long long)(m0 + mf*16 + rr) * HWX + n0 + nf*8 + cc;
            long long r1 = r0 + 8*HWX;
            out[r0]   = d[mf][nf][0];
            out[r0+1] = d[mf][nf][1];
            out[r1]   = d[mf][nf][2];
            out[r1+1] = d[mf][nf][3];
        }
}

// ---------------- kernel 1: dilated conv + relu + 1x1 + softmax -> sw ------
__global__ void __launch_bounds__(128) convsw_kernel(
    const float* __restrict__ cen, const float* __restrict__ w1a,
    const float* __restrict__ b1a, const float* __restrict__ w2a,
    const float* __restrict__ b2a, const float* __restrict__ sumwa,
    float* __restrict__ swa)
{
    int ish = blockIdx.y;
    int d = 1 << ish;
    const float* w1 = w1a + ish*9216;
    const float* b1 = b1a + ish*32;
    const float* w2 = w2a + ish*256;
    const float* b2 = b2a + ish*8;
    const float* sumw = sumwa + ish*2;
    float* sw = swa + (long long)ish*Bb*8*HWX;

    __shared__ float s_w1[32*9*32];
    __shared__ float s_w2[8*32];
    __shared__ float s_b1[32];
    __shared__ float s_b2[8];
    int tid = threadIdx.x;
    for (int idx = tid; idx < 9216; idx += 128) {
        int o = idx / 288; int rem = idx % 288; int ci = rem / 9; int t = rem % 9;
        s_w1[(ci*9 + t)*32 + o] = w1[idx];
    }
    for (int idx = tid; idx < 256; idx += 128) s_w2[idx] = w2[idx];
    if (tid < 32) s_b1[tid] = b1[tid];
    if (tid < 8)  s_b2[tid] = b2[tid];
    __syncthreads();

    int b = blockIdx.x >> 7;
    int y = blockIdx.x & 127;
    int x = tid;

    float acc[32];
    #pragma unroll
    for (int o = 0; o < 32; o++) acc[o] = 0.f;

    const float* cb = cen + ((long long)b*32) * HWX;
    for (int ci = 0; ci < 32; ci++) {
        float v[9];
        #pragma unroll
        for (int ky = 0; ky < 3; ky++) {
            int ry = y + (ky-1)*d;
            bool yok = (ry >= 0 && ry < Hd);
            #pragma unroll
            for (int kx = 0; kx < 3; kx++) {
                int cx = x + (kx-1)*d;
                bool ok = yok && (cx >= 0) && (cx < Wd);
                v[ky*3+kx] = ok ? cb[ci*HWX + ry*Wd + cx] : 0.f;
            }
        }
        #pragma unroll
        for (int t = 0; t < 9; t++) {
            const float4* wp = (const float4*)&s_w1[(ci*9+t)*32];
            float vv = v[t];
            #pragma unroll
            for (int o4 = 0; o4 < 8; o4++) {
                float4 w = wp[o4];
                acc[o4*4+0] += vv*w.x; acc[o4*4+1] += vv*w.y;
                acc[o4*4+2] += vv*w.z; acc[o4*4+3] += vv*w.w;
            }
        }
    }

    float lg[8];
    #pragma unroll
    for (int k = 0; k < 8; k++) lg[k] = s_b2[k];
    #pragma unroll
    for (int o = 0; o < 32; o++) {
        float h = acc[o] + s_b1[o]; h = h > 0.f ? h : 0.f;
        #pragma unroll
        for (int k = 0; k < 8; k++) lg[k] += h * s_w2[k*32 + o];
    }
    float mx = lg[0];
    #pragma unroll
    for (int k = 1; k < 8; k++) mx = fmaxf(mx, lg[k]);
    float e[8], se = 0.f;
    #pragma unroll
    for (int k = 0; k < 8; k++) { e[k] = expf(lg[k]-mx); se += e[k]; }

    float a0 = sumw[0], a1 = sumw[1];
    float am = fmaxf(a0, a1);
    float e0 = expf(a0-am), e1 = expf(a1-am);
    float g0 = e0/(e0+e1);
    float scale = g0 / se;

    long long pix = (long long)y*Wd + x;
    #pragma unroll
    for (int k = 0; k < 8; k++)
        sw[(((long long)(b*8+k)) << 14) + pix] = e[k]*scale;
}

// ---------------- kernel 2: neighbors -> Z (bf16 hi/lo), all shifts --------
__global__ void __launch_bounds__(256) sur_kernel(
    const float* __restrict__ cen, const float* __restrict__ swa,
    const float* __restrict__ sumwa,
    __nv_bfloat16* __restrict__ Zhi, __nv_bfloat16* __restrict__ Zlo)
{
    int ik = blockIdx.y;
    int d = 1 << ik;
    const float* sw = swa + (long long)ik*Bb*8*HWX;
    const float* sumw = sumwa + ik*2;

    int t = blockIdx.x * 256 + threadIdx.x;
    int b = t >> 19;
    int c = (t >> 14) & 31;
    int s = t & 16383;
    int y = s >> 7, x = s & 127;

    float a0 = sumw[0], a1 = sumw[1];
    float am = fmaxf(a0, a1);
    float e0 = expf(a0-am), e1 = expf(a1-am);
    float g0 = e0/(e0+e1), g1 = e1/(e0+e1);

    int ym = y-d; ym = ym < 0 ? -ym : ym;
    int yp = y+d; yp = yp > 127 ? 254 - yp : yp;
    int xm = x-d; xm = xm < 0 ? -xm : xm;
    int xp = x+d; xp = xp > 127 ? 254 - xp : xp;

    const float* base = cen + (((long long)(b*32 + c)) << 14);
    float nb[8];
    nb[0]=base[ym*128+xm]; nb[1]=base[ym*128+x]; nb[2]=base[ym*128+xp];
    nb[3]=base[y *128+xm];                       nb[4]=base[y *128+xp];
    nb[5]=base[yp*128+xm]; nb[6]=base[yp*128+x]; nb[7]=base[yp*128+xp];
    float cv = base[y*128+x];

    float sumx = cv * g1;
    float mean = 0.f;
    #pragma unroll
    for (int k = 0; k < 8; k++) {
        float swv = sw[(((long long)(b*8+k)) << 14) + s];
        sumx += nb[k]*swv;
        mean += nb[k];
    }
    mean *= 0.125f;
    long long zb = (long long)b*1152*HWX;

    float vc = mean*g0 + cv*g1;
    {
        __nv_bfloat16 h = __float2bfloat16(vc);
        __nv_bfloat16 l = __float2bfloat16(vc - __bfloat162float(h));
        long long idx = zb + (long long)(1024 + ik*32 + c)*HWX + s;
        Zhi[idx] = h; Zlo[idx] = l;
    }
    #pragma unroll
    for (int k = 0; k < 8; k++) {
        float v = nb[k] - sumx;
        __nv_bfloat16 h = __float2bfloat16(v);
        __nv_bfloat16 l = __float2bfloat16(v - __bfloat162float(h));
        long long idx = zb + (long long)(ik*256 + k*32 + c)*HWX + s;
        Zhi[idx] = h; Zlo[idx] = l;
    }
}

// ---------------- gram reduce + scatter -------------------------------------
__global__ void __launch_bounds__(256) gramred_kernel(
    const float* __restrict__ part, float* __restrict__ Gq,
    float* __restrict__ M, float* __restrict__ Gc)
{
    int idx = blockIdx.x*256 + threadIdx.x;
    int b = idx / (21*16384);
    int rem = idx - b*21*16384;
    int tile = rem >> 14;
    int e = rem & 16383;
    float v = 0.f;
    const float* p = part + (((long long)(b*21 + tile)*7) << 14) + e;
    #pragma unroll
    for (int s = 0; s < 7; s++) v += p[(long long)s << 14];
    int r = e >> 7, c = e & 127;
    if (tile < 12) {
        int ik = tile/3, sub = tile - ik*3;
        int gr = (sub==2 ? 128:0) + r;
        int gc = (sub==0 ? 0:128) + c;
        float* G = Gq + (long long)(b*4+ik)*65536;
        G[gr*256 + gc] = v;
        if (sub == 1) G[gc*256 + gr] = v;
    } else if (tile < 20) {
        int cb = tile - 12;
        M[(long long)b*131072 + r*1024 + cb*128 + c] = v;
    } else {
        Gc[(long long)b*16384 + r*128 + c] = v;
    }
}

// ---------------- kn = sqrt(diag(kw G kw^T)) — smem-tiled -------------------
#define KN_PITCH 260
#define KN_SMEM  (2*32*KN_PITCH*4)

__global__ void __launch_bounds__(256) kn_kernel(
    const float* __restrict__ kw, const float* __restrict__ Gq,
    float* __restrict__ kn)
{
    extern __shared__ float kdyn[];
    float* Wsh = kdyn;
    float* Gs  = kdyn + 32*KN_PITCH;
    int z = blockIdx.y;
    int ik = z & 3;
    int rbase = blockIdx.x * 32;
    const float* W = kw + (long long)ik*512*256 + (long long)rbase*256;
    const float* G = Gq + (long long)z*65536;
    int tid = threadIdx.x;
    for (int idx = tid; idx < 8192; idx += 256) {
        int r = idx >> 8, i = idx & 255;
        Wsh[r*KN_PITCH + i] = W[r*256 + i];
    }
    __syncthreads();
    int r = tid >> 3, seg = tid & 7;
    float acc = 0.f;
    for (int jt = 0; jt < 8; jt++) {
        for (int idx = tid; idx < 8192; idx += 256) {
            int jj = idx >> 8, i = idx & 255;
            Gs[jj*KN_PITCH + i] = G[(jt*32 + jj)*256 + i];
        }
        __syncthreads();
        #pragma unroll 4
        for (int jj = 0; jj < 32; jj++) {
            const float* gr = &Gs[jj*KN_PITCH + seg*32];
            const float* wr = &Wsh[r*KN_PITCH + seg*32];
            float dd = 0.f;
            #pragma unroll
            for (int ii = 0; ii < 32; ii++) dd += gr[ii]*wr[ii];
            acc += Wsh[r*KN_PITCH + jt*32 + jj] * dd;
        }
        __syncthreads();
    }
    acc += __shfl_xor_sync(0xffffffffu, acc, 4);
    acc += __shfl_xor_sync(0xffffffffu, acc, 2);
    acc += __shfl_xor_sync(0xffffffffu, acc, 1);
    if (seg == 0)
        kn[z*512 + rbase + r] = fmaxf(sqrtf(fmaxf(acc, 0.f)), 1e-12f);
}

// ---------------- qn = sqrt(diag(qw Gc qw^T)) -------------------------------
__global__ void __launch_bounds__(64) qn_kernel(
    const float* __restrict__ qw, const float* __restrict__ Gc,
    float* __restrict__ qn)
{
    int z = blockIdx.x;
    int b = z >> 2, iq = z & 3;
    __shared__ float Gs[32*33];
    int tid = threadIdx.x;
    for (int idx = tid; idx < 1024; idx += 64) {
        int r = idx >> 5, c = idx & 31;
        Gs[r*33 + c] = Gc[(long long)b*16384 + (iq*32+r)*128 + iq*32 + c];
    }
    __syncthreads();
    const float* w = qw + iq*2048 + tid*32;
    float wr[32];
    #pragma unroll
    for (int i = 0; i < 32; i++) wr[i] = w[i];
    float acc = 0.f;
    #pragma unroll
    for (int i = 0; i < 32; i++) {
        float s = 0.f;
        #pragma unroll
        for (int j = 0; j < 32; j++) s += Gs[i*33+j]*wr[j];
        acc += wr[i]*s;
    }
    qn[z*64 + tid] = fmaxf(sqrtf(fmaxf(acc, 0.f)), 1e-12f);
}

// ---------------- score assembly: S = qw M kw^T, scaled ---------------------
__global__ void __launch_bounds__(128) scoreasm_kernel(
    const float* __restrict__ qw, const float* __restrict__ kw,
    const float* __restrict__ M,  const float* __restrict__ qn,
    const float* __restrict__ kn, float* __restrict__ score)
{
    int bid = blockIdx.x;
    int b  = bid >> 6;
    int n  = (bid >> 4) & 3;
    int iq = (bid >> 2) & 3;
    int ik = bid & 3;
    int tid = threadIdx.x;

    __shared__ float qws[16*32];
    __shared__ float P[16*256];
    __shared__ float buf[32*132];

    for (int idx = tid; idx < 512; idx += 128) {
        int o = idx >> 5, ch = idx & 31;
        qws[o*32 + ch] = qw[iq*2048 + (16*n + o)*32 + ch];
    }
    __syncthreads();

    const float* Mb = M + (long long)b*131072 + (long long)(iq*32)*1024 + ik*256;
    for (int h = 0; h < 2; h++) {
        for (int idx = tid; idx < 4096; idx += 128) {
            int ch = idx >> 7, cl = idx & 127;
            buf[ch*132 + cl] = Mb[(long long)ch*1024 + h*128 + cl];
        }
        __syncthreads();
        int o = tid >> 3, cg = tid & 7;
        #pragma unroll
        for (int j = 0; j < 16; j++) {
            int cl = cg*16 + j;
            float s = 0.f;
            #pragma unroll
            for (int ch = 0; ch < 32; ch++) s += qws[o*32+ch]*buf[ch*132+cl];
            P[o*256 + h*128 + cl] = s;
        }
        __syncthreads();
    }

    float acc[16] = {};
    const float* Kw = kw + (long long)ik*512*256 + (long long)(128*n)*256;
    for (int h2 = 0; h2 < 8; h2++) {
        for (int i = 0; i < 32; i++) {
            int idx = i*128 + tid;
            int row = idx >> 5, j = idx & 31;
            buf[j*132 + row] = Kw[(long long)row*256 + h2*32 + j];
        }
        __syncthreads();
        #pragma unroll
        for (int j = 0; j < 32; j++) {
            float kv = buf[j*132 + tid];
            #pragma unroll
            for (int o = 0; o < 16; o++)
                acc[o] += P[o*256 + h2*32 + j] * kv;
        }
        __syncthreads();
    }

    float knv = kn[(b*4+ik)*512 + 128*n + tid];
    #pragma unroll
    for (int o = 0; o < 16; o++) {
        float qnv = qn[(b*4+iq)*64 + 16*n + o];
        float v = acc[o] / (128.f * qnv * knv);
        int q = 4*o + iq, k = 4*tid + ik;
        score[((long long)(b*4+n)*64 + q)*512 + k] = v;
    }
}

// ---------------- InstanceNorm + softmax (in place) -------------------------
__global__ void __launch_bounds__(1024) insoftmax_kernel(float* __restrict__ score)
{
    int bn = blockIdx.x;
    int tid = threadIdx.x;
    float s1 = 0.f, s2 = 0.f;
    for (int e = tid; e < 32768; e += 1024) {
        float v = score[((long long)bn << 15) + e];
        s1 += v; s2 += v*v;
    }
    __shared__ float r1[32], r2[32];
    s1 = warpsum(s1); s2 = warpsum(s2);
    int w = tid >> 5, l = tid & 31;
    if (l == 0) { r1[w] = s1; r2[w] = s2; }
    __syncthreads();
    __shared__ float smu, srstd;
    if (tid == 0) {
        float t1 = 0.f, t2 = 0.f;
        #pragma unroll
        for (int i = 0; i < 32; i++) { t1 += r1[i]; t2 += r2[i]; }
        float mu  = t1 / 32768.f;
        float var = fmaxf(t2/32768.f - mu*mu, 0.f);
        smu = mu; srstd = rsqrtf(var + 1e-5f);
    }
    __syncthreads();
    float mu = smu, rstd = srstd;
    #pragma unroll
    for (int qq = 0; qq < 2; qq++) {
        int q = w*2 + qq;
        float v[16];
        float mx = -1e30f;
        #pragma unroll
        for (int j = 0; j < 16; j++) {
            v[j] = (score[((long long)bn << 15) + q*512 + l + j*32] - mu) * rstd;
            mx = fmaxf(mx, v[j]);
        }
        #pragma unroll
        for (int o = 16; o > 0; o >>= 1) mx = fmaxf(mx, __shfl_xor_sync(~0u, mx, o));
        float sum = 0.f;
        #pragma unroll
        for (int j = 0; j < 16; j++) { v[j] = expf(v[j]-mx); sum += v[j]; }
        sum = warpsum(sum);
        float invs = 1.f / sum;
        #pragma unroll
        for (int j = 0; j < 16; j++)
            score[((long long)bn << 15) + q*512 + l + j*32] = v[j]*invs;
    }
}

// ---------------- ucat ------------------------------------------------------
__global__ void __launch_bounds__(256) ucat_kernel(
    const float* __restrict__ attn, const float* __restrict__ vw,
    float* __restrict__ ucat)
{
    int bid = blockIdx.x;
    int b  = bid >> 4;
    int ik = (bid >> 2) & 3;
    int n  = bid & 3;
    int tid = threadIdx.x;

    __shared__ float A[64*128];
    for (int idx = tid; idx < 8192; idx += 256) {
        int q = idx >> 7, cp = idx & 127;
        A[idx] = attn[((long long)(b*4+n)*64 + q)*512 + 4*cp + ik];
    }
    __syncthreads();

    float acc[64] = {};
    const float* V = vw + (long long)ik*512*256 + (long long)(128*n)*256;
    for (int cp = 0; cp < 128; cp++) {
        float wv = V[(long long)cp*256 + tid];
        #pragma unroll
        for (int q = 0; q < 64; q++)
            acc[q] += A[q*128 + cp] * wv;
    }
    float* uo = ucat + (long long)b*262144 + (long long)(n*64)*1024 + ik*256 + tid;
    #pragma unroll
    for (int q = 0; q < 64; q++)
        uo[(long long)q*1024] = acc[q];
}

// ---------------- wcat SGEMM with fused bf16 hi/lo epilogue -----------------
__global__ void __launch_bounds__(256) sgemm_wcat(
    const float* __restrict__ A, const float* __restrict__ B,
    __nv_bfloat16* __restrict__ Whi, __nv_bfloat16* __restrict__ Wlo)
{
    const int N = 1024, K = 256;
    B   += (long long)blockIdx.z * 262144;
    Whi += (long long)blockIdx.z * 262144;
    Wlo += (long long)blockIdx.z * 262144;
    int m0 = blockIdx.y * 64;
    int n0 = blockIdx.x * 128;
    __shared__ float As[16][64];
    __shared__ float Bs[16][128];
    int tid = threadIdx.x;
    int tx = tid & 15, ty = tid >> 4;
    float acc[4][8] = {};
    int am = tid >> 2, ak = (tid & 3) * 4;

    for (int kt = 0; kt < K; kt += 16) {
        float4 av = *(const float4*)&A[(long long)(m0+am)*K + kt + ak];
        As[ak+0][am] = av.x; As[ak+1][am] = av.y;
        As[ak+2][am] = av.z; As[ak+3][am] = av.w;
        #pragma unroll
        for (int i = 0; i < 2; i++) {
            int idx = tid + i*256;
            int k = idx >> 5, n4 = idx & 31;
            *(float4*)&Bs[k][n4*4] = *(const float4*)&B[(long long)(kt+k)*N + n0 + n4*4];
        }
        __syncthreads();
        #pragma unroll
        for (int k = 0; k < 16; k++) {
            float4 a4 = *(const float4*)&As[k][ty*4];
            float4 b0 = *(const float4*)&Bs[k][tx*4];
            float4 b1 = *(const float4*)&Bs[k][64 + tx*4];
            float a[4]  = {a4.x,a4.y,a4.z,a4.w};
            float bb[8] = {b0.x,b0.y,b0.z,b0.w,b1.x,b1.y,b1.z,b1.w};
            #pragma unroll
            for (int i = 0; i < 4; i++)
                #pragma unroll
                for (int j = 0; j < 8; j++)
                    acc[i][j] += a[i]*bb[j];
        }
        __syncthreads();
    }
    #pragma unroll
    for (int i = 0; i < 4; i++) {
        long long r = (long long)(m0 + ty*4 + i) * N;
        #pragma unroll
        for (int half = 0; half < 2; half++) {
            __nv_bfloat16 hv[4], lv[4];
            #pragma unroll
            for (int j = 0; j < 4; j++) {
                float v = acc[i][half*4 + j];
                __nv_bfloat16 h = __float2bfloat16(v);
                hv[j] = h;
                lv[j] = __float2bfloat16(v - __bfloat162float(h));
            }
            long long off = r + n0 + half*64 + tx*4;
            *(uint2*)&Whi[off] = *(const uint2*)hv;
            *(uint2*)&Wlo[off] = *(const uint2*)lv;
        }
    }
}

// ---------------- BatchNorm stats + normalize/relu -------------------------
__global__ void __launch_bounds__(256) bnstats_kernel(
    const float* __restrict__ y, float* __restrict__ mv)
{
    int o = blockIdx.x;
    float s1 = 0.f, s2 = 0.f;
    for (int idx = threadIdx.x; idx < 8192; idx += 256) {
        int b = idx >> 12, s4 = idx & 4095;
        float4 v4 = *(const float4*)&y[(((long long)(b*256 + o)) << 14) + s4*4];
        s1 += v4.x + v4.y + v4.z + v4.w;
        s2 += v4.x*v4.x + v4.y*v4.y + v4.z*v4.z + v4.w*v4.w;
    }
    s1 = warpsum(s1); s2 = warpsum(s2);
    __shared__ float r1[8], r2[8];
    int w = threadIdx.x >> 5, l = threadIdx.x & 31;
    if (l == 0) { r1[w] = s1; r2[w] = s2; }
    __syncthreads();
    if (threadIdx.x == 0) {
        float t1 = 0.f, t2 = 0.f;
        #pragma unroll
        for (int i = 0; i < 8; i++) { t1 += r1[i]; t2 += r2[i]; }
        float mean = t1 / 32768.f;
        float var  = fmaxf(t2/32768.f - mean*mean, 0.f);
        mv[o*2]   = mean;
        mv[o*2+1] = rsqrtf(var + 1e-5f);
    }
}

__global__ void __launch_bounds__(256) bnrelu_kernel(
    const float* __restrict__ y, const float* __restrict__ mv,
    const float* __restrict__ gamma, const float* __restrict__ beta,
    float* __restrict__ out)
{
    long long t4 = (long long)blockIdx.x * 256 + threadIdx.x;
    int o = (int)((t4 >> 12) & 255);
    float mean = mv[o*2], rstd = mv[o*2+1];
    float ga = gamma[o], be = beta[o];
    float4 v = *(const float4*)&y[t4*4];
    v.x = fmaxf((v.x-mean)*rstd*ga + be, 0.f);
    v.y = fmaxf((v.y-mean)*rstd*ga + be, 0.f);
    v.z = fmaxf((v.z-mean)*rstd*ga + be, 0.f);
    v.w = fmaxf((v.w-mean)*rstd*ga + be, 0.f);
    *(float4*)&out[t4*4] = v;
}

// ---------------- host side -------------------------------------------------
extern "C" void kernel_launch(void* const* d_in, const int* in_sizes, int n_in,
                              void* d_out, int out_size)
{
    (void)in_sizes; (void)n_in; (void)out_size;
    const float* cen   = (const float*)d_in[0];
    const float* q_w   = (const float*)d_in[1];
    const float* k_w   = (const float*)d_in[2];
    const float* v_w   = (const float*)d_in[3];
    const float* sw1   = (const float*)d_in[4];
    const float* sb1   = (const float*)d_in[5];
    const float* sw2   = (const float*)d_in[6];
    const float* sb2   = (const float*)d_in[7];
    const float* sumw  = (const float*)d_in[8];
    const float* out_w = (const float*)d_in[9];
    const float* gamma = (const float*)d_in[10];
    const float* beta  = (const float*)d_in[11];
    float* out = (float*)d_out;

    float *p_sw,*p_part,*p_Gq,*p_M,*p_Gc,*p_kn,*p_qn,*p_score,*p_ucat,*p_y,*p_bn;
    __nv_bfloat16 *p_Zhi,*p_Zlo,*p_whi,*p_wlo;
    cudaGetSymbolAddress((void**)&p_sw,   g_sw);
    cudaGetSymbolAddress((void**)&p_Zhi,  g_Zhi);
    cudaGetSymbolAddress((void**)&p_Zlo,  g_Zlo);
    cudaGetSymbolAddress((void**)&p_part, g_part);
    cudaGetSymbolAddress((void**)&p_Gq,   g_Gq);
    cudaGetSymbolAddress((void**)&p_M,    g_M);
    cudaGetSymbolAddress((void**)&p_Gc,   g_Gc);
    cudaGetSymbolAddress((void**)&p_kn,   g_kn);
    cudaGetSymbolAddress((void**)&p_qn,   g_qn);
    cudaGetSymbolAddress((void**)&p_score,g_score);
    cudaGetSymbolAddress((void**)&p_ucat, g_ucat);
    cudaGetSymbolAddress((void**)&p_whi,  g_whi);
    cudaGetSymbolAddress((void**)&p_wlo,  g_wlo);
    cudaGetSymbolAddress((void**)&p_y,    g_y);
    cudaGetSymbolAddress((void**)&p_bn,   g_bn);

    cudaFuncSetAttribute(mma_gram_kernel, cudaFuncAttributeMaxDynamicSharedMemorySize, DSMEM_BYTES);
    cudaFuncSetAttribute(mma_y_kernel,    cudaFuncAttributeMaxDynamicSharedMemorySize, Y_DSMEM);
    cudaFuncSetAttribute(kn_kernel,       cudaFuncAttributeMaxDynamicSharedMemorySize, KN_SMEM);

    convsw_kernel<<<dim3(Bb*Hd, 4), 128>>>(cen, sw1, sb1, sw2, sb2, sumw, p_sw);
    sur_kernel<<<dim3(4096, 4), 256>>>(cen, p_sw, sumw, p_Zhi, p_Zlo);
    mma_gram_kernel<<<dim3(21, 7, Bb), 256, DSMEM_BYTES>>>(p_Zhi, p_Zlo, p_part);
    gramred_kernel<<<Bb*21*64, 256>>>(p_part, p_Gq, p_M, p_Gc);
    kn_kernel<<<dim3(16, Bb*4), 256, KN_SMEM>>>(k_w, p_Gq, p_kn);
    qn_kernel<<<Bb*4, 64>>>(q_w, p_Gc, p_qn);
    scoreasm_kernel<<<128, 128>>>(q_w, k_w, p_M, p_qn, p_kn, p_score);
    insoftmax_kernel<<<8, 1024>>>(p_score);
    ucat_kernel<<<Bb*16, 256>>>(p_score, v_w, p_ucat);
    sgemm_wcat<<<dim3(8, 4, Bb), 256>>>(out_w, p_ucat, p_whi, p_wlo);
    mma_y_kernel<<<dim3(128, 2, Bb), 256, Y_DSMEM>>>(p_whi, p_wlo, p_Zhi, p_Zlo, p_y);
    bnstats_kernel<<<256, 256>>>(p_y, p_bn);
    bnrelu_kernel<<<8192, 256>>>(p_y, p_bn, gamma, beta, out);
}

// round 17
// speedup vs baseline: 1.0220x; 1.0063x over previous
#include <cuda_runtime.h>
#include <cuda_bf16.h>
#include <math.h>
#include <stdint.h>

#define HWX 16384
#define Wd  128
#define Hd  128
#define Bb  2

// ---------------- device scratch (no runtime alloc allowed) ----------------
__device__ float g_sw  [4*Bb*8*HWX];
__device__ __nv_bfloat16 g_Zhi[Bb*1152*HWX];
__device__ __nv_bfloat16 g_Zlo[Bb*1152*HWX];
__device__ float g_part[Bb*21*8*16384];
__device__ float g_Gq  [Bb*4*256*256];
__device__ float g_M   [Bb*128*1024];
__device__ float g_Gc  [Bb*128*128];
__device__ float g_kn  [Bb*4*512];
__device__ float g_qn  [Bb*4*64];
__device__ float g_score[8*64*512];
__device__ float g_ucat[Bb*256*1024];
__device__ __nv_bfloat16 g_whi[Bb*256*1024];
__device__ __nv_bfloat16 g_wlo[Bb*256*1024];
__device__ float g_y   [Bb*256*HWX];
__device__ float g_bnp [256*256*2];     // per-(nblk,b) channel partials
__device__ float g_bn  [512];

__constant__ int c_tr0[21] = {0,0,128, 256,256,384, 512,512,640, 768,768,896,
                              1024,1024,1024,1024,1024,1024,1024,1024, 1024};
__constant__ int c_tc0[21] = {0,128,128, 256,384,384, 512,640,640, 768,896,896,
                              0,128,256,384,512,640,768,896, 1024};

__device__ __forceinline__ float warpsum(float v) {
    #pragma unroll
    for (int o = 16; o > 0; o >>= 1) v += __shfl_xor_sync(0xffffffffu, v, o);
    return v;
}

// ====================== warp-MMA helpers (family-safe PTX) ==================
__device__ __forceinline__ uint32_t smem_u32(const void* p) {
    uint32_t a;
    asm("{ .reg .u64 t; cvta.to.shared.u64 t, %1; cvt.u32.u64 %0, t; }" : "=r"(a) : "l"(p));
    return a;
}
__device__ __forceinline__ void cp16(uint32_t dst, const void* src) {
    asm volatile("cp.async.cg.shared.global [%0], [%1], 16;" :: "r"(dst), "l"(src));
}
__device__ __forceinline__ void cp_commit() {
    asm volatile("cp.async.commit_group;");
}
__device__ __forceinline__ void ldmat4(uint32_t* r, uint32_t addr) {
    asm volatile("ldmatrix.sync.aligned.m8n8.x4.shared.b16 {%0,%1,%2,%3}, [%4];"
        : "=r"(r[0]),"=r"(r[1]),"=r"(r[2]),"=r"(r[3]) : "r"(addr));
}
__device__ __forceinline__ void ldmat2(uint32_t* r, uint32_t addr) {
    asm volatile("ldmatrix.sync.aligned.m8n8.x2.shared.b16 {%0,%1}, [%2];"
        : "=r"(r[0]),"=r"(r[1]) : "r"(addr));
}
__device__ __forceinline__ void ldmat2_trans(uint32_t* r, uint32_t addr) {
    asm volatile("ldmatrix.sync.aligned.m8n8.x2.trans.shared.b16 {%0,%1}, [%2];"
        : "=r"(r[0]),"=r"(r[1]) : "r"(addr));
}
__device__ __forceinline__ void mma16816(float* d, const uint32_t* a, const uint32_t* b) {
    asm volatile("mma.sync.aligned.m16n8k16.row.col.f32.bf16.bf16.f32 "
        "{%0,%1,%2,%3}, {%4,%5,%6,%7}, {%8,%9}, {%0,%1,%2,%3};"
        : "+f"(d[0]),"+f"(d[1]),"+f"(d[2]),"+f"(d[3])
        : "r"(a[0]),"r"(a[1]),"r"(a[2]),"r"(a[3]), "r"(b[0]),"r"(b[1]));
}

#define SPITCH_B 80                  // bytes per smem row (32 bf16 + 8 pad)
#define TILE_B   (128*SPITCH_B)      // 10240
#define STAGE_B  (4*TILE_B)          // 40960
#define DSMEM_BYTES (2*STAGE_B)      // 81920 -> 2 CTAs/SM

// ---------------- bf16-split warp-MMA core (NT, k-major; 2-stage) -----------
__device__ __forceinline__ void mma_core(
    const __nv_bfloat16* __restrict__ Ahi, const __nv_bfloat16* __restrict__ Alo,
    const __nv_bfloat16* __restrict__ Bhi, const __nv_bfloat16* __restrict__ Blo,
    long long pa, long long pb, int nchunks,
    float* __restrict__ out, long long ldo, int diag)
{
    extern __shared__ char dyn[];
    uint32_t sbase = smem_u32(dyn);
    int tid = threadIdx.x, lane = tid & 31, wid = tid >> 5;
    int m0 = (wid >> 2) * 64;
    int n0 = (wid & 3) * 32;

    const __nv_bfloat16* srcs[4] = {Ahi, Alo, Bhi, Blo};

    float d[4][4][4];
    #pragma unroll
    for (int i = 0; i < 4; i++)
        #pragma unroll
        for (int j = 0; j < 4; j++)
            #pragma unroll
            for (int k = 0; k < 4; k++) d[i][j][k] = 0.f;

    {
        #pragma unroll
        for (int i = 0; i < 8; i++) {
            int idx = tid + i*256;
            int t = idx >> 9;
            if (diag && t >= 2) continue;
            int rc = idx & 511, row = rc >> 2, c8 = rc & 3;
            const __nv_bfloat16* src = srcs[t] + (long long)row*((t < 2) ? pa : pb) + c8*8;
            cp16(sbase + t*TILE_B + row*SPITCH_B + c8*16, src);
        }
        cp_commit();
    }

    for (int c = 0; c < nchunks; c++) {
        int s = c & 1;
        if (c + 1 < nchunks) {
            long long koff = (long long)(c+1) * 32;
            uint32_t st = sbase + (s^1)*STAGE_B;
            #pragma unroll
            for (int i = 0; i < 8; i++) {
                int idx = tid + i*256;
                int t = idx >> 9;
                if (diag && t >= 2) continue;
                int rc = idx & 511, row = rc >> 2, c8 = rc & 3;
                const __nv_bfloat16* src = srcs[t] + (long long)row*((t < 2) ? pa : pb) + koff + c8*8;
                cp16(st + t*TILE_B + row*SPITCH_B + c8*16, src);
            }
            cp_commit();
            asm volatile("cp.async.wait_group 1;");
        } else {
            asm volatile("cp.async.wait_group 0;");
        }
        __syncthreads();

        uint32_t stA = sbase + s*STAGE_B;
        uint32_t stB = stA + (diag ? 0 : 2*TILE_B);
        int arow = lane & 15;
        int acol = ((lane >> 4) & 1) * 16;
        int brow = lane & 7;
        int bcol = ((lane >> 3) & 1) * 16;

        #pragma unroll
        for (int ks = 0; ks < 2; ks++) {
            uint32_t aHi[4][4], aLo[4][4], bHi[4][2], bLo[4][2];
            #pragma unroll
            for (int mf = 0; mf < 4; mf++) {
                uint32_t addr = stA + (m0 + mf*16 + arow)*SPITCH_B + ks*32 + acol;
                ldmat4(aHi[mf], addr);
                ldmat4(aLo[mf], addr + TILE_B);
            }
            #pragma unroll
            for (int nf = 0; nf < 4; nf++) {
                uint32_t addr = stB + (n0 + nf*8 + brow)*SPITCH_B + ks*32 + bcol;
                ldmat2(bHi[nf], addr);
                ldmat2(bLo[nf], addr + TILE_B);
            }
            #pragma unroll
            for (int mf = 0; mf < 4; mf++)
                #pragma unroll
                for (int nf = 0; nf < 4; nf++)
                    mma16816(d[mf][nf], aHi[mf], bHi[nf]);
            #pragma unroll
            for (int mf = 0; mf < 4; mf++)
                #pragma unroll
                for (int nf = 0; nf < 4; nf++)
                    mma16816(d[mf][nf], aHi[mf], bLo[nf]);
            #pragma unroll
            for (int mf = 0; mf < 4; mf++)
                #pragma unroll
                for (int nf = 0; nf < 4; nf++)
                    mma16816(d[mf][nf], aLo[mf], bHi[nf]);
        }
        __syncthreads();
    }

    int rr = lane >> 2, cc = (lane & 3) * 2;
    #pragma unroll
    for (int mf = 0; mf < 4; mf++)
        #pragma unroll
        for (int nf = 0; nf < 4; nf++) {
            long long r0 = (long long)(m0 + mf*16 + rr) * ldo + n0 + nf*8 + cc;
            long long r1 = r0 + 8*ldo;
            out[r0]   = d[mf][nf][0];
            out[r0+1] = d[mf][nf][1];
            out[r1]   = d[mf][nf][2];
            out[r1+1] = d[mf][nf][3];
        }
}

// gram: K = 16384 = 512 chunks of 32; 7 splits: split0 = 74 chunks, splits 1..6 = 73
__global__ void __launch_bounds__(256,2) mma_gram_kernel(
    const __nv_bfloat16* __restrict__ Zhi, const __nv_bfloat16* __restrict__ Zlo,
    float* __restrict__ part)
{
    int tile = blockIdx.x, split = blockIdx.y, b = blockIdx.z;
    int koff = (split == 0) ? 0 : 32*(73*split + 1);
    int nch  = (split == 0) ? 74 : 73;
    int diag = (c_tr0[tile] == c_tc0[tile]) ? 1 : 0;
    long long ab = ((long long)(b*1152 + c_tr0[tile]))*HWX + koff;
    long long bb = ((long long)(b*1152 + c_tc0[tile]))*HWX + koff;
    float* out = part + (((long long)((b*21 + tile)*7 + split)) << 14);
    mma_core(Zhi+ab, Zlo+ab, Zhi+bb, Zlo+bb, HWX, HWX, nch, out, 128, diag);
}

// ---------------- mma_y: NN GEMM + fused BN-stats partial epilogue ----------
#define Y_APITCH 80
#define Y_ATILE  (128*Y_APITCH)          // 10240
#define Y_BPITCH 272                     // 128 bf16 (256B) + 16 pad
#define Y_BTILE  (32*Y_BPITCH)           // 8704
#define Y_BOFF   (2*Y_ATILE)             // 20480
#define Y_STAGE  (2*Y_ATILE + 2*Y_BTILE) // 37888
#define Y_DSMEM  (2*Y_STAGE)             // 75776

__global__ void __launch_bounds__(256,2) mma_y_kernel(
    const __nv_bfloat16* __restrict__ Whi, const __nv_bfloat16* __restrict__ Wlo,
    const __nv_bfloat16* __restrict__ Zhi, const __nv_bfloat16* __restrict__ Zlo,
    float* __restrict__ y, float* __restrict__ gpart)
{
    extern __shared__ char dyn[];
    uint32_t sbase = smem_u32(dyn);
    int n0g = blockIdx.x * 128, m0g = blockIdx.y * 128, b = blockIdx.z;
    const __nv_bfloat16* Ahi = Whi + (long long)(b*256 + m0g) * 1024;
    const __nv_bfloat16* Alo = Wlo + (long long)(b*256 + m0g) * 1024;
    const __nv_bfloat16* Bhi = Zhi + (long long)(b*1152)*HWX + n0g;
    const __nv_bfloat16* Blo = Zlo + (long long)(b*1152)*HWX + n0g;
    float* out = y + (long long)(b*256 + m0g)*HWX + n0g;

    int tid = threadIdx.x, lane = tid & 31, wid = tid >> 5;
    int m0 = (wid >> 2) * 64;
    int n0 = (wid & 3) * 32;

    float d[4][4][4];
    #pragma unroll
    for (int i = 0; i < 4; i++)
        #pragma unroll
        for (int j = 0; j < 4; j++)
            #pragma unroll
            for (int k = 0; k < 4; k++) d[i][j][k] = 0.f;

    auto load_chunk = [&](uint32_t st, int kc) {
        long long koff = (long long)kc * 32;
        #pragma unroll
        for (int i = 0; i < 4; i++) {
            int idx = tid + i*256;
            int t = idx >> 9, rc = idx & 511, row = rc >> 2, c8 = rc & 3;
            const __nv_bfloat16* src = (t ? Alo : Ahi) + (long long)row*1024 + koff + c8*8;
            cp16(st + t*Y_ATILE + row*Y_APITCH + c8*16, src);
        }
        #pragma unroll
        for (int i = 0; i < 4; i++) {
            int idx = tid + i*256;
            int t = idx >> 9, rc = idx & 511, krow = rc >> 4, c16 = idx & 15;
            const __nv_bfloat16* src = (t ? Blo : Bhi) + (koff + krow)*(long long)HWX + c16*8;
            cp16(st + Y_BOFF + t*Y_BTILE + krow*Y_BPITCH + c16*16, src);
        }
        cp_commit();
    };

    load_chunk(sbase, 0);

    const int nchunks = 32;
    for (int c = 0; c < nchunks; c++) {
        int s = c & 1;
        if (c + 1 < nchunks) {
            load_chunk(sbase + (s^1)*Y_STAGE, c+1);
            asm volatile("cp.async.wait_group 1;");
        } else {
            asm volatile("cp.async.wait_group 0;");
        }
        __syncthreads();

        uint32_t stA = sbase + s*Y_STAGE;
        int arow = lane & 15;
        int acol = ((lane >> 4) & 1) * 16;
        int bk = lane & 15;

        #pragma unroll
        for (int ks = 0; ks < 2; ks++) {
            uint32_t aHi[4][4], aLo[4][4], bHi[4][2], bLo[4][2];
            #pragma unroll
            for (int mf = 0; mf < 4; mf++) {
                uint32_t addr = stA + (m0 + mf*16 + arow)*Y_APITCH + ks*32 + acol;
                ldmat4(aHi[mf], addr);
                ldmat4(aLo[mf], addr + Y_ATILE);
            }
            #pragma unroll
            for (int nf = 0; nf < 4; nf++) {
                uint32_t addr = stA + Y_BOFF + (ks*16 + bk)*Y_BPITCH + (n0 + nf*8)*2;
                ldmat2_trans(bHi[nf], addr);
                ldmat2_trans(bLo[nf], addr + Y_BTILE);
            }
            #pragma unroll
            for (int mf = 0; mf < 4; mf++)
                #pragma unroll
                for (int nf = 0; nf < 4; nf++)
                    mma16816(d[mf][nf], aHi[mf], bHi[nf]);
            #pragma unroll
            for (int mf = 0; mf < 4; mf++)
                #pragma unroll
                for (int nf = 0; nf < 4; nf++)
                    mma16816(d[mf][nf], aHi[mf], bLo[nf]);
            #pragma unroll
            for (int mf = 0; mf < 4; mf++)
                #pragma unroll
                for (int nf = 0; nf < 4; nf++)
                    mma16816(d[mf][nf], aLo[mf], bHi[nf]);
        }
        __syncthreads();
    }

    int rr = lane >> 2, cc = (lane & 3) * 2;
    #pragma unroll
    for (int mf = 0; mf < 4; mf++)
        #pragma unroll
        for (int nf = 0; nf < 4; nf++) {
            long long r0 = (long long)(m0 + mf*16 + rr) * HWX + n0 + nf*8 + cc;
            long long r1 = r0 + 8*HWX;
            out[r0]   = d[mf][nf][0];
            out[r0+1] = d[mf][nf][1];
            out[r1]   = d[mf][nf][2];
            out[r1+1] = d[mf][nf][3];
        }

    // ---- fused BN-stats partials (channel = m0g + row; summed over n,b later)
    float* sb1 = (float*)dyn;            // [4 slots][128 rows]
    float* sb2 = sb1 + 512;              // [4 slots][128 rows]
    int slot = wid & 3;
    #pragma unroll
    for (int mf = 0; mf < 4; mf++) {
        float a1 = 0.f, a2 = 0.f, b1 = 0.f, b2 = 0.f;
        #pragma unroll
        for (int nf = 0; nf < 4; nf++) {
            float v0 = d[mf][nf][0], v1 = d[mf][nf][1];
            float v2 = d[mf][nf][2], v3 = d[mf][nf][3];
            a1 += v0 + v1;       a2 += v0*v0 + v1*v1;
            b1 += v2 + v3;       b2 += v2*v2 + v3*v3;
        }
        a1 += __shfl_xor_sync(~0u, a1, 1); a1 += __shfl_xor_sync(~0u, a1, 2);
        a2 += __shfl_xor_sync(~0u, a2, 1); a2 += __shfl_xor_sync(~0u, a2, 2);
        b1 += __shfl_xor_sync(~0u, b1, 1); b1 += __shfl_xor_sync(~0u, b1, 2);
        b2 += __shfl_xor_sync(~0u, b2, 1); b2 += __shfl_xor_sync(~0u, b2, 2);
        if ((lane & 3) == 0) {
            int ra = m0 + mf*16 + rr;
            sb1[slot*128 + ra]     = a1;
            sb2[slot*128 + ra]     = a2;
            sb1[slot*128 + ra + 8] = b1;
            sb2[slot*128 + ra + 8] = b2;
        }
    }
    __syncthreads();
    if (tid < 128) {
        float t1 = sb1[tid] + sb1[128+tid] + sb1[256+tid] + sb1[384+tid];
        float t2 = sb2[tid] + sb2[128+tid] + sb2[256+tid] + sb2[384+tid];
        int pslot = blockIdx.x + 128*b;                 // 0..255
        long long gi = ((long long)pslot*256 + (m0g + tid))*2;
        gpart[gi]   = t1;
        gpart[gi+1] = t2;
    }
}

// ---------------- bnred: fold 256 partials per channel -> mean/rstd ---------
__global__ void __launch_bounds__(256) bnred_kernel(
    const float* __restrict__ gpart, float* __restrict__ mv)
{
    int ch = blockIdx.x;                 // 0..255
    int tid = threadIdx.x;               // 256
    float s1 = gpart[((long long)tid*256 + ch)*2];
    float s2 = gpart[((long long)tid*256 + ch)*2 + 1];
    s1 = warpsum(s1); s2 = warpsum(s2);
    __shared__ float r1[8], r2[8];
    int w = tid >> 5, l = tid & 31;
    if (l == 0) { r1[w] = s1; r2[w] = s2; }
    __syncthreads();
    if (tid == 0) {
        float t1 = 0.f, t2 = 0.f;
        #pragma unroll
        for (int i = 0; i < 8; i++) { t1 += r1[i]; t2 += r2[i]; }
        float mean = t1 / 32768.f;
        float var  = fmaxf(t2/32768.f - mean*mean, 0.f);
        mv[ch*2]   = mean;
        mv[ch*2+1] = rsqrtf(var + 1e-5f);
    }
}

// ---------------- kernel 1: dilated conv + relu + 1x1 + softmax -> sw ------
__global__ void __launch_bounds__(128) convsw_kernel(
    const float* __restrict__ cen, const float* __restrict__ w1a,
    const float* __restrict__ b1a, const float* __restrict__ w2a,
    const float* __restrict__ b2a, const float* __restrict__ sumwa,
    float* __restrict__ swa)
{
    int ish = blockIdx.y;
    int d = 1 << ish;
    const float* w1 = w1a + ish*9216;
    const float* b1 = b1a + ish*32;
    const float* w2 = w2a + ish*256;
    const float* b2 = b2a + ish*8;
    const float* sumw = sumwa + ish*2;
    float* sw = swa + (long long)ish*Bb*8*HWX;

    __shared__ float s_w1[32*9*32];
    __shared__ float s_w2[8*32];
    __shared__ float s_b1[32];
    __shared__ float s_b2[8];
    int tid = threadIdx.x;
    for (int idx = tid; idx < 9216; idx += 128) {
        int o = idx / 288; int rem = idx % 288; int ci = rem / 9; int t = rem % 9;
        s_w1[(ci*9 + t)*32 + o] = w1[idx];
    }
    for (int idx = tid; idx < 256; idx += 128) s_w2[idx] = w2[idx];
    if (tid < 32) s_b1[tid] = b1[tid];
    if (tid < 8)  s_b2[tid] = b2[tid];
    __syncthreads();

    int b = blockIdx.x >> 7;
    int y = blockIdx.x & 127;
    int x = tid;

    float acc[32];
    #pragma unroll
    for (int o = 0; o < 32; o++) acc[o] = 0.f;

    const float* cb = cen + ((long long)b*32) * HWX;
    for (int ci = 0; ci < 32; ci++) {
        float v[9];
        #pragma unroll
        for (int ky = 0; ky < 3; ky++) {
            int ry = y + (ky-1)*d;
            bool yok = (ry >= 0 && ry < Hd);
            #pragma unroll
            for (int kx = 0; kx < 3; kx++) {
                int cx = x + (kx-1)*d;
                bool ok = yok && (cx >= 0) && (cx < Wd);
                v[ky*3+kx] = ok ? cb[ci*HWX + ry*Wd + cx] : 0.f;
            }
        }
        #pragma unroll
        for (int t = 0; t < 9; t++) {
            const float4* wp = (const float4*)&s_w1[(ci*9+t)*32];
            float vv = v[t];
            #pragma unroll
            for (int o4 = 0; o4 < 8; o4++) {
                float4 w = wp[o4];
                acc[o4*4+0] += vv*w.x; acc[o4*4+1] += vv*w.y;
                acc[o4*4+2] += vv*w.z; acc[o4*4+3] += vv*w.w;
            }
        }
    }

    float lg[8];
    #pragma unroll
    for (int k = 0; k < 8; k++) lg[k] = s_b2[k];
    #pragma unroll
    for (int o = 0; o < 32; o++) {
        float h = acc[o] + s_b1[o]; h = h > 0.f ? h : 0.f;
        #pragma unroll
        for (int k = 0; k < 8; k++) lg[k] += h * s_w2[k*32 + o];
    }
    float mx = lg[0];
    #pragma unroll
    for (int k = 1; k < 8; k++) mx = fmaxf(mx, lg[k]);
    float e[8], se = 0.f;
    #pragma unroll
    for (int k = 0; k < 8; k++) { e[k] = expf(lg[k]-mx); se += e[k]; }

    float a0 = sumw[0], a1 = sumw[1];
    float am = fmaxf(a0, a1);
    float e0 = expf(a0-am), e1 = expf(a1-am);
    float g0 = e0/(e0+e1);
    float scale = g0 / se;

    long long pix = (long long)y*Wd + x;
    #pragma unroll
    for (int k = 0; k < 8; k++)
        sw[(((long long)(b*8+k)) << 14) + pix] = e[k]*scale;
}

// ---------------- kernel 2: neighbors -> Z (bf16 hi/lo), all shifts --------
__global__ void __launch_bounds__(256) sur_kernel(
    const float* __restrict__ cen, const float* __restrict__ swa,
    const float* __restrict__ sumwa,
    __nv_bfloat16* __restrict__ Zhi, __nv_bfloat16* __restrict__ Zlo)
{
    int ik = blockIdx.y;
    int d = 1 << ik;
    const float* sw = swa + (long long)ik*Bb*8*HWX;
    const float* sumw = sumwa + ik*2;

    int t = blockIdx.x * 256 + threadIdx.x;
    int b = t >> 19;
    int c = (t >> 14) & 31;
    int s = t & 16383;
    int y = s >> 7, x = s & 127;

    float a0 = sumw[0], a1 = sumw[1];
    float am = fmaxf(a0, a1);
    float e0 = expf(a0-am), e1 = expf(a1-am);
    float g0 = e0/(e0+e1), g1 = e1/(e0+e1);

    int ym = y-d; ym = ym < 0 ? -ym : ym;
    int yp = y+d; yp = yp > 127 ? 254 - yp : yp;
    int xm = x-d; xm = xm < 0 ? -xm : xm;
    int xp = x+d; xp = xp > 127 ? 254 - xp : xp;

    const float* base = cen + (((long long)(b*32 + c)) << 14);
    float nb[8];
    nb[0]=base[ym*128+xm]; nb[1]=base[ym*128+x]; nb[2]=base[ym*128+xp];
    nb[3]=base[y *128+xm];                       nb[4]=base[y *128+xp];
    nb[5]=base[yp*128+xm]; nb[6]=base[yp*128+x]; nb[7]=base[yp*128+xp];
    float cv = base[y*128+x];

    float sumx = cv * g1;
    float mean = 0.f;
    #pragma unroll
    for (int k = 0; k < 8; k++) {
        float swv = sw[(((long long)(b*8+k)) << 14) + s];
        sumx += nb[k]*swv;
        mean += nb[k];
    }
    mean *= 0.125f;
    long long zb = (long long)b*1152*HWX;

    float vc = mean*g0 + cv*g1;
    {
        __nv_bfloat16 h = __float2bfloat16(vc);
        __nv_bfloat16 l = __float2bfloat16(vc - __bfloat162float(h));
        long long idx = zb + (long long)(1024 + ik*32 + c)*HWX + s;
        Zhi[idx] = h; Zlo[idx] = l;
    }
    #pragma unroll
    for (int k = 0; k < 8; k++) {
        float v = nb[k] - sumx;
        __nv_bfloat16 h = __float2bfloat16(v);
        __nv_bfloat16 l = __float2bfloat16(v - __bfloat162float(h));
        long long idx = zb + (long long)(ik*256 + k*32 + c)*HWX + s;
        Zhi[idx] = h; Zlo[idx] = l;
    }
}

// ---------------- gram reduce + scatter -------------------------------------
__global__ void __launch_bounds__(256) gramred_kernel(
    const float* __restrict__ part, float* __restrict__ Gq,
    float* __restrict__ M, float* __restrict__ Gc)
{
    int idx = blockIdx.x*256 + threadIdx.x;
    int b = idx / (21*16384);
    int rem = idx - b*21*16384;
    int tile = rem >> 14;
    int e = rem & 16383;
    float v = 0.f;
    const float* p = part + (((long long)(b*21 + tile)*7) << 14) + e;
    #pragma unroll
    for (int s = 0; s < 7; s++) v += p[(long long)s << 14];
    int r = e >> 7, c = e & 127;
    if (tile < 12) {
        int ik = tile/3, sub = tile - ik*3;
        int gr = (sub==2 ? 128:0) + r;
        int gc = (sub==0 ? 0:128) + c;
        float* G = Gq + (long long)(b*4+ik)*65536;
        G[gr*256 + gc] = v;
        if (sub == 1) G[gc*256 + gr] = v;
    } else if (tile < 20) {
        int cb = tile - 12;
        M[(long long)b*131072 + r*1024 + cb*128 + c] = v;
    } else {
        Gc[(long long)b*16384 + r*128 + c] = v;
    }
}

// ---------------- kn = sqrt(diag(kw G kw^T)) — smem-tiled -------------------
#define KN_PITCH 260
#define KN_SMEM  (2*32*KN_PITCH*4)

__global__ void __launch_bounds__(256) kn_kernel(
    const float* __restrict__ kw, const float* __restrict__ Gq,
    float* __restrict__ kn)
{
    extern __shared__ float kdyn[];
    float* Wsh = kdyn;
    float* Gs  = kdyn + 32*KN_PITCH;
    int z = blockIdx.y;
    int ik = z & 3;
    int rbase = blockIdx.x * 32;
    const float* W = kw + (long long)ik*512*256 + (long long)rbase*256;
    const float* G = Gq + (long long)z*65536;
    int tid = threadIdx.x;
    for (int idx = tid; idx < 8192; idx += 256) {
        int r = idx >> 8, i = idx & 255;
        Wsh[r*KN_PITCH + i] = W[r*256 + i];
    }
    __syncthreads();
    int r = tid >> 3, seg = tid & 7;
    float acc = 0.f;
    for (int jt = 0; jt < 8; jt++) {
        for (int idx = tid; idx < 8192; idx += 256) {
            int jj = idx >> 8, i = idx & 255;
            Gs[jj*KN_PITCH + i] = G[(jt*32 + jj)*256 + i];
        }
        __syncthreads();
        #pragma unroll 4
        for (int jj = 0; jj < 32; jj++) {
            const float* gr = &Gs[jj*KN_PITCH + seg*32];
            const float* wr = &Wsh[r*KN_PITCH + seg*32];
            float dd = 0.f;
            #pragma unroll
            for (int ii = 0; ii < 32; ii++) dd += gr[ii]*wr[ii];
            acc += Wsh[r*KN_PITCH + jt*32 + jj] * dd;
        }
        __syncthreads();
    }
    acc += __shfl_xor_sync(0xffffffffu, acc, 4);
    acc += __shfl_xor_sync(0xffffffffu, acc, 2);
    acc += __shfl_xor_sync(0xffffffffu, acc, 1);
    if (seg == 0)
        kn[z*512 + rbase + r] = fmaxf(sqrtf(fmaxf(acc, 0.f)), 1e-12f);
}

// ---------------- qn = sqrt(diag(qw Gc qw^T)) -------------------------------
__global__ void __launch_bounds__(64) qn_kernel(
    const float* __restrict__ qw, const float* __restrict__ Gc,
    float* __restrict__ qn)
{
    int z = blockIdx.x;
    int b = z >> 2, iq = z & 3;
    __shared__ float Gs[32*33];
    int tid = threadIdx.x;
    for (int idx = tid; idx < 1024; idx += 64) {
        int r = idx >> 5, c = idx & 31;
        Gs[r*33 + c] = Gc[(long long)b*16384 + (iq*32+r)*128 + iq*32 + c];
    }
    __syncthreads();
    const float* w = qw + iq*2048 + tid*32;
    float wr[32];
    #pragma unroll
    for (int i = 0; i < 32; i++) wr[i] = w[i];
    float acc = 0.f;
    #pragma unroll
    for (int i = 0; i < 32; i++) {
        float s = 0.f;
        #pragma unroll
        for (int j = 0; j < 32; j++) s += Gs[i*33+j]*wr[j];
        acc += wr[i]*s;
    }
    qn[z*64 + tid] = fmaxf(sqrtf(fmaxf(acc, 0.f)), 1e-12f);
}

// ---------------- score assembly: S = qw M kw^T, scaled ---------------------
__global__ void __launch_bounds__(128) scoreasm_kernel(
    const float* __restrict__ qw, const float* __restrict__ kw,
    const float* __restrict__ M,  const float* __restrict__ qn,
    const float* __restrict__ kn, float* __restrict__ score)
{
    int bid = blockIdx.x;
    int b  = bid >> 6;
    int n  = (bid >> 4) & 3;
    int iq = (bid >> 2) & 3;
    int ik = bid & 3;
    int tid = threadIdx.x;

    __shared__ float qws[16*32];
    __shared__ float P[16*256];
    __shared__ float buf[32*132];

    for (int idx = tid; idx < 512; idx += 128) {
        int o = idx >> 5, ch = idx & 31;
        qws[o*32 + ch] = qw[iq*2048 + (16*n + o)*32 + ch];
    }
    __syncthreads();

    const float* Mb = M + (long long)b*131072 + (long long)(iq*32)*1024 + ik*256;
    for (int h = 0; h < 2; h++) {
        for (int idx = tid; idx < 4096; idx += 128) {
            int ch = idx >> 7, cl = idx & 127;
            buf[ch*132 + cl] = Mb[(long long)ch*1024 + h*128 + cl];
        }
        __syncthreads();
        int o = tid >> 3, cg = tid & 7;
        #pragma unroll
        for (int j = 0; j < 16; j++) {
            int cl = cg*16 + j;
            float s = 0.f;
            #pragma unroll
            for (int ch = 0; ch < 32; ch++) s += qws[o*32+ch]*buf[ch*132+cl];
            P[o*256 + h*128 + cl] = s;
        }
        __syncthreads();
    }

    float acc[16] = {};
    const float* Kw = kw + (long long)ik*512*256 + (long long)(128*n)*256;
    for (int h2 = 0; h2 < 8; h2++) {
        for (int i = 0; i < 32; i++) {
            int idx = i*128 + tid;
            int row = idx >> 5, j = idx & 31;
            buf[j*132 + row] = Kw[(long long)row*256 + h2*32 + j];
        }
        __syncthreads();
        #pragma unroll
        for (int j = 0; j < 32; j++) {
            float kv = buf[j*132 + tid];
            #pragma unroll
            for (int o = 0; o < 16; o++)
                acc[o] += P[o*256 + h2*32 + j] * kv;
        }
        __syncthreads();
    }

    float knv = kn[(b*4+ik)*512 + 128*n + tid];
    #pragma unroll
    for (int o = 0; o < 16; o++) {
        float qnv = qn[(b*4+iq)*64 + 16*n + o];
        float v = acc[o] / (128.f * qnv * knv);
        int q = 4*o + iq, k = 4*tid + ik;
        score[((long long)(b*4+n)*64 + q)*512 + k] = v;
    }
}

// ---------------- InstanceNorm + softmax (in place) -------------------------
__global__ void __launch_bounds__(1024) insoftmax_kernel(float* __restrict__ score)
{
    int bn = blockIdx.x;
    int tid = threadIdx.x;
    float s1 = 0.f, s2 = 0.f;
    for (int e = tid; e < 32768; e += 1024) {
        float v = score[((long long)bn << 15) + e];
        s1 += v; s2 += v*v;
    }
    __shared__ float r1[32], r2[32];
    s1 = warpsum(s1); s2 = warpsum(s2);
    int w = tid >> 5, l = tid & 31;
    if (l == 0) { r1[w] = s1; r2[w] = s2; }
    __syncthreads();
    __shared__ float smu, srstd;
    if (tid == 0) {
        float t1 = 0.f, t2 = 0.f;
        #pragma unroll
        for (int i = 0; i < 32; i++) { t1 += r1[i]; t2 += r2[i]; }
        float mu  = t1 / 32768.f;
        float var = fmaxf(t2/32768.f - mu*mu, 0.f);
        smu = mu; srstd = rsqrtf(var + 1e-5f);
    }
    __syncthreads();
    float mu = smu, rstd = srstd;
    #pragma unroll
    for (int qq = 0; qq < 2; qq++) {
        int q = w*2 + qq;
        float v[16];
        float mx = -1e30f;
        #pragma unroll
        for (int j = 0; j < 16; j++) {
            v[j] = (score[((long long)bn << 15) + q*512 + l + j*32] - mu) * rstd;
            mx = fmaxf(mx, v[j]);
        }
        #pragma unroll
        for (int o = 16; o > 0; o >>= 1) mx = fmaxf(mx, __shfl_xor_sync(~0u, mx, o));
        float sum = 0.f;
        #pragma unroll
        for (int j = 0; j < 16; j++) { v[j] = expf(v[j]-mx); sum += v[j]; }
        sum = warpsum(sum);
        float invs = 1.f / sum;
        #pragma unroll
        for (int j = 0; j < 16; j++)
            score[((long long)bn << 15) + q*512 + l + j*32] = v[j]*invs;
    }
}

// ---------------- ucat ------------------------------------------------------
__global__ void __launch_bounds__(256) ucat_kernel(
    const float* __restrict__ attn, const float* __restrict__ vw,
    float* __restrict__ ucat)
{
    int bid = blockIdx.x;
    int b  = bid >> 4;
    int ik = (bid >> 2) & 3;
    int n  = bid & 3;
    int tid = threadIdx.x;

    __shared__ float A[64*128];
    for (int idx = tid; idx < 8192; idx += 256) {
        int q = idx >> 7, cp = idx & 127;
        A[idx] = attn[((long long)(b*4+n)*64 + q)*512 + 4*cp + ik];
    }
    __syncthreads();

    float acc[64] = {};
    const float* V = vw + (long long)ik*512*256 + (long long)(128*n)*256;
    for (int cp = 0; cp < 128; cp++) {
        float wv = V[(long long)cp*256 + tid];
        #pragma unroll
        for (int q = 0; q < 64; q++)
            acc[q] += A[q*128 + cp] * wv;
    }
    float* uo = ucat + (long long)b*262144 + (long long)(n*64)*1024 + ik*256 + tid;
    #pragma unroll
    for (int q = 0; q < 64; q++)
        uo[(long long)q*1024] = acc[q];
}

// ---------------- wcat SGEMM with fused bf16 hi/lo epilogue -----------------
__global__ void __launch_bounds__(256) sgemm_wcat(
    const float* __restrict__ A, const float* __restrict__ B,
    __nv_bfloat16* __restrict__ Whi, __nv_bfloat16* __restrict__ Wlo)
{
    const int N = 1024, K = 256;
    B   += (long long)blockIdx.z * 262144;
    Whi += (long long)blockIdx.z * 262144;
    Wlo += (long long)blockIdx.z * 262144;
    int m0 = blockIdx.y * 64;
    int n0 = blockIdx.x * 128;
    __shared__ float As[16][64];
    __shared__ float Bs[16][128];
    int tid = threadIdx.x;
    int tx = tid & 15, ty = tid >> 4;
    float acc[4][8] = {};
    int am = tid >> 2, ak = (tid & 3) * 4;

    for (int kt = 0; kt < K; kt += 16) {
        float4 av = *(const float4*)&A[(long long)(m0+am)*K + kt + ak];
        As[ak+0][am] = av.x; As[ak+1][am] = av.y;
        As[ak+2][am] = av.z; As[ak+3][am] = av.w;
        #pragma unroll
        for (int i = 0; i < 2; i++) {
            int idx = tid + i*256;
            int k = idx >> 5, n4 = idx & 31;
            *(float4*)&Bs[k][n4*4] = *(const float4*)&B[(long long)(kt+k)*N + n0 + n4*4];
        }
        __syncthreads();
        #pragma unroll
        for (int k = 0; k < 16; k++) {
            float4 a4 = *(const float4*)&As[k][ty*4];
            float4 b0 = *(const float4*)&Bs[k][tx*4];
            float4 b1 = *(const float4*)&Bs[k][64 + tx*4];
            float a[4]  = {a4.x,a4.y,a4.z,a4.w};
            float bb[8] = {b0.x,b0.y,b0.z,b0.w,b1.x,b1.y,b1.z,b1.w};
            #pragma unroll
            for (int i = 0; i < 4; i++)
                #pragma unroll
                for (int j = 0; j < 8; j++)
                    acc[i][j] += a[i]*bb[j];
        }
        __syncthreads();
    }
    #pragma unroll
    for (int i = 0; i < 4; i++) {
        long long r = (long long)(m0 + ty*4 + i) * N;
        #pragma unroll
        for (int half = 0; half < 2; half++) {
            __nv_bfloat16 hv[4], lv[4];
            #pragma unroll
            for (int j = 0; j < 4; j++) {
                float v = acc[i][half*4 + j];
                __nv_bfloat16 h = __float2bfloat16(v);
                hv[j] = h;
                lv[j] = __float2bfloat16(v - __bfloat162float(h));
            }
            long long off = r + n0 + half*64 + tx*4;
            *(uint2*)&Whi[off] = *(const uint2*)hv;
            *(uint2*)&Wlo[off] = *(const uint2*)lv;
        }
    }
}

// ---------------- BN apply + relu -------------------------------------------
__global__ void __launch_bounds__(256) bnrelu_kernel(
    const float* __restrict__ y, const float* __restrict__ mv,
    const float* __restrict__ gamma, const float* __restrict__ beta,
    float* __restrict__ out)
{
    long long t4 = (long long)blockIdx.x * 256 + threadIdx.x;
    int o = (int)((t4 >> 12) & 255);
    float mean = mv[o*2], rstd = mv[o*2+1];
    float ga = gamma[o], be = beta[o];
    float4 v = *(const float4*)&y[t4*4];
    v.x = fmaxf((v.x-mean)*rstd*ga + be, 0.f);
    v.y = fmaxf((v.y-mean)*rstd*ga + be, 0.f);
    v.z = fmaxf((v.z-mean)*rstd*ga + be, 0.f);
    v.w = fmaxf((v.w-mean)*rstd*ga + be, 0.f);
    *(float4*)&out[t4*4] = v;
}

// ---------------- host side -------------------------------------------------
extern "C" void kernel_launch(void* const* d_in, const int* in_sizes, int n_in,
                              void* d_out, int out_size)
{
    (void)in_sizes; (void)n_in; (void)out_size;
    const float* cen   = (const float*)d_in[0];
    const float* q_w   = (const float*)d_in[1];
    const float* k_w   = (const float*)d_in[2];
    const float* v_w   = (const float*)d_in[3];
    const float* sw1   = (const float*)d_in[4];
    const float* sb1   = (const float*)d_in[5];
    const float* sw2   = (const float*)d_in[6];
    const float* sb2   = (const float*)d_in[7];
    const float* sumw  = (const float*)d_in[8];
    const float* out_w = (const float*)d_in[9];
    const float* gamma = (const float*)d_in[10];
    const float* beta  = (const float*)d_in[11];
    float* out = (float*)d_out;

    float *p_sw,*p_part,*p_Gq,*p_M,*p_Gc,*p_kn,*p_qn,*p_score,*p_ucat,*p_y,*p_bnp,*p_bn;
    __nv_bfloat16 *p_Zhi,*p_Zlo,*p_whi,*p_wlo;
    cudaGetSymbolAddress((void**)&p_sw,   g_sw);
    cudaGetSymbolAddress((void**)&p_Zhi,  g_Zhi);
    cudaGetSymbolAddress((void**)&p_Zlo,  g_Zlo);
    cudaGetSymbolAddress((void**)&p_part, g_part);
    cudaGetSymbolAddress((void**)&p_Gq,   g_Gq);
    cudaGetSymbolAddress((void**)&p_M,    g_M);
    cudaGetSymbolAddress((void**)&p_Gc,   g_Gc);
    cudaGetSymbolAddress((void**)&p_kn,   g_kn);
    cudaGetSymbolAddress((void**)&p_qn,   g_qn);
    cudaGetSymbolAddress((void**)&p_score,g_score);
    cudaGetSymbolAddress((void**)&p_ucat, g_ucat);
    cudaGetSymbolAddress((void**)&p_whi,  g_whi);
    cudaGetSymbolAddress((void**)&p_wlo,  g_wlo);
    cudaGetSymbolAddress((void**)&p_y,    g_y);
    cudaGetSymbolAddress((void**)&p_bnp,  g_bnp);
    cudaGetSymbolAddress((void**)&p_bn,   g_bn);

    cudaFuncSetAttribute(mma_gram_kernel, cudaFuncAttributeMaxDynamicSharedMemorySize, DSMEM_BYTES);
    cudaFuncSetAttribute(mma_y_kernel,    cudaFuncAttributeMaxDynamicSharedMemorySize, Y_DSMEM);
    cudaFuncSetAttribute(kn_kernel,       cudaFuncAttributeMaxDynamicSharedMemorySize, KN_SMEM);

    convsw_kernel<<<dim3(Bb*Hd, 4), 128>>>(cen, sw1, sb1, sw2, sb2, sumw, p_sw);
    sur_kernel<<<dim3(4096, 4), 256>>>(cen, p_sw, sumw, p_Zhi, p_Zlo);
    mma_gram_kernel<<<dim3(21, 7, Bb), 256, DSMEM_BYTES>>>(p_Zhi, p_Zlo, p_part);
    gramred_kernel<<<Bb*21*64, 256>>>(p_part, p_Gq, p_M, p_Gc);
    kn_kernel<<<dim3(16, Bb*4), 256, KN_SMEM>>>(k_w, p_Gq, p_kn);
    qn_kernel<<<Bb*4, 64>>>(q_w, p_Gc, p_qn);
    scoreasm_kernel<<<128, 128>>>(q_w, k_w, p_M, p_qn, p_kn, p_score);
    insoftmax_kernel<<<8, 1024>>>(p_score);
    ucat_kernel<<<Bb*16, 256>>>(p_score, v_w, p_ucat);
    sgemm_wcat<<<dim3(8, 4, Bb), 256>>>(out_w, p_ucat, p_whi, p_wlo);
    mma_y_kernel<<<dim3(128, 2, Bb), 256, Y_DSMEM>>>(p_whi, p_wlo, p_Zhi, p_Zlo, p_y, p_bnp);
    bnred_kernel<<<256, 256>>>(p_bnp, p_bn);
    bnrelu_kernel<<<8192, 256>>>(p_y, p_bn, gamma, beta, out);
}